// round 9
// baseline (speedup 1.0000x reference)
#include <cuda_runtime.h>
#include <math.h>

// ---------------- problem constants ----------------
#define NPRO 60000
#define NWAT 40000
#define NN   100000
#define EE   1000000
#define INDIM 21
#define HIDC  32
#define HEADS 4
#define HC    128
#define EK    32
#define EDIM  32
#define FFH   128
#define ODIM  2
#define RADMAX 5.0f

#define FOLD_ME   0
#define FOLD_AEC  256
#define FOLD_ASD1 264
#define FOLD_ASD2 520
#define FOLD_HW   1544

// ---------------- static device scratch ----------------
__device__ int   g_src[EE];
__device__ int   g_dst[EE];
__device__ float g_ae[EE * 8];
__device__ int   g_csr_src[EE];
__device__ float g_csr_ae[EE * 8];
__device__ int   g_rowptr[NN + 1];
__device__ int   g_cnt[NN];
__device__ int   g_cur[NN];
__device__ int   g_bsum[128];
__device__ float g_h0[NN * HIDC];
__device__ float g_x[(size_t)NN * HC];
__device__ float g_h1[(size_t)NN * HC];
__device__ float g_h2[(size_t)NWAT * HC];
__device__ float g_asd[NN * 8];
__device__ float g_fold[2048];

__device__ __forceinline__ float lrelu(float x) { return fmaxf(x, 0.2f * x); }

// ---------------- fold kernel ----------------
__global__ void fold_kernel(const float* __restrict__ We,  const float* __restrict__ be,
                            const float* __restrict__ Wedge1, const float* __restrict__ atte1,
                            const float* __restrict__ Wedge2, const float* __restrict__ atte2,
                            const float* __restrict__ W1, const float* __restrict__ atts1, const float* __restrict__ attd1,
                            const float* __restrict__ W2, const float* __restrict__ atts2, const float* __restrict__ attd2,
                            const float* __restrict__ Wf, const float* __restrict__ bf) {
    __shared__ float Ve[2][EDIM][HEADS];
    int t = threadIdx.x;
    if (t < 256) {
        int l = t >> 7, r = t & 127, d = r >> 2, h = r & 3;
        const float* Wg = l ? Wedge2 : Wedge1;
        const float* ae = l ? atte2 : atte1;
        float s = 0.f;
        #pragma unroll
        for (int c = 0; c < 32; c++) s = fmaf(Wg[d * HC + h * 32 + c], ae[h * 32 + c], s);
        Ve[l][d][h] = s;
    }
    __syncthreads();
    if (t < 256) {
        int k = t >> 3, j = t & 7, l = j >> 2, h = j & 3;
        float s = 0.f;
        #pragma unroll
        for (int d = 0; d < 32; d++) s = fmaf(We[k * 32 + d], Ve[l][d][h], s);
        g_fold[FOLD_ME + k * 8 + j] = s;
    }
    if (t < 8) {
        int l = t >> 2, h = t & 3;
        float s = 0.f;
        for (int d = 0; d < 32; d++) s = fmaf(be[d], Ve[l][d][h], s);
        g_fold[FOLD_AEC + t] = s;
    }
    if (t < 256) {
        int d = t >> 3, j = t & 7, h = j & 3;
        const float* att = (j < 4) ? atts1 : attd1;
        float s = 0.f;
        #pragma unroll
        for (int c = 0; c < 32; c++) s = fmaf(W1[d * HC + h * 32 + c], att[h * 32 + c], s);
        g_fold[FOLD_ASD1 + d * 8 + j] = s;
    }
    for (int i = t; i < 1024; i += 256) {
        int d = i >> 3, j = i & 7, h = j & 3;
        const float* att = (j < 4) ? atts2 : attd2;
        float s = 0.f;
        #pragma unroll
        for (int c = 0; c < 32; c++) s = fmaf(W2[d * HC + h * 32 + c], att[h * 32 + c], s);
        g_fold[FOLD_ASD2 + i] = s;
    }
    if (t < 32) g_fold[FOLD_HW + t] = Wf[(INDIM - 1) * HIDC + t] + bf[t];
}

__global__ void zero_kernel() {
    int i = blockIdx.x * 256 + threadIdx.x;
    if (i < NN) { g_cnt[i] = 0; g_cur[i] = 0; }
}

// ---------------- edge prep (int32 indices confirmed by R8 diagnostics) ----------------
__global__ void edge_prep(const int* __restrict__ ei,
                          const float* __restrict__ ppos, const float* __restrict__ wpos,
                          const float* __restrict__ gamma) {
    __shared__ float sMe[256];
    __shared__ float sAec[8];
    int t = threadIdx.x;
    if (t < 256) sMe[t] = g_fold[FOLD_ME + t];
    if (t < 8)   sAec[t] = g_fold[FOLD_AEC + t];
    __syncthreads();
    int e = blockIdx.x * 256 + t;
    if (e >= EE) return;
    int s = ei[e];
    int d = ei[EE + e];
    if ((unsigned)s >= NN) s = 0;
    if ((unsigned)d >= NN) d = 0;
    g_src[e] = s; g_dst[e] = d;
    atomicAdd(&g_cnt[d], 1);
    const float* ps = (s < NPRO) ? (ppos + 3 * s) : (wpos + 3 * (s - NPRO));
    const float* pd = (d < NPRO) ? (ppos + 3 * d) : (wpos + 3 * (d - NPRO));
    float dx = pd[0] - ps[0], dy = pd[1] - ps[1], dz = pd[2] - ps[2];
    float dis = sqrtf(dx * dx + dy * dy + dz * dz);
    float g = gamma[0];
    float acc[8];
    #pragma unroll
    for (int j = 0; j < 8; j++) acc[j] = sAec[j];
    #pragma unroll
    for (int k = 0; k < 32; k++) {
        float tt = dis - (float)k * (RADMAX / 31.0f);
        float r = __expf(-g * tt * tt);
        #pragma unroll
        for (int j = 0; j < 8; j++) acc[j] = fmaf(r, sMe[k * 8 + j], acc[j]);
    }
    float4* ap = (float4*)&g_ae[(size_t)e * 8];
    ap[0] = make_float4(acc[0], acc[1], acc[2], acc[3]);
    ap[1] = make_float4(acc[4], acc[5], acc[6], acc[7]);
}

// ---------------- scan ----------------
__global__ void scan1_kernel() {
    __shared__ int sm[1024];
    int tid = threadIdx.x;
    int i = blockIdx.x * 1024 + tid;
    int v = (i < NN) ? g_cnt[i] : 0;
    sm[tid] = v;
    __syncthreads();
    for (int off = 1; off < 1024; off <<= 1) {
        int t = (tid >= off) ? sm[tid - off] : 0;
        __syncthreads();
        sm[tid] += t;
        __syncthreads();
    }
    if (i < NN) g_rowptr[i] = sm[tid] - v;
    if (tid == 1023) g_bsum[blockIdx.x] = sm[1023];
}
__global__ void scan2_kernel(int nb) {
    int run = 0;
    for (int b = 0; b < nb; b++) { int v = g_bsum[b]; g_bsum[b] = run; run += v; }
    g_rowptr[NN] = run;
}
__global__ void scan3_kernel() {
    int i = blockIdx.x * 256 + threadIdx.x;
    if (i < NN) g_rowptr[i] += g_bsum[i >> 10];
}

__global__ void scatter_kernel() {
    int e = blockIdx.x * 256 + threadIdx.x;
    if (e >= EE) return;
    int d = g_dst[e];
    int p = atomicAdd(&g_cur[d], 1);
    int idx = g_rowptr[d] + p;
    g_csr_src[idx] = g_src[e];
    const float4* sp = (const float4*)&g_ae[(size_t)e * 8];
    float4* dp = (float4*)&g_csr_ae[(size_t)idx * 8];
    dp[0] = sp[0];
    dp[1] = sp[1];
}

// ---------------- h0 ----------------
__global__ void h0_kernel(const float* __restrict__ pf, const float* __restrict__ Wf,
                          const float* __restrict__ bf) {
    __shared__ float sW[INDIM * HIDC];
    __shared__ float sb[HIDC];
    __shared__ float shw[HIDC];
    int t = threadIdx.x;
    for (int i = t; i < INDIM * HIDC; i += 256) sW[i] = Wf[i];
    if (t < HIDC) { sb[t] = bf[t]; shw[t] = g_fold[FOLD_HW + t]; }
    __syncthreads();
    int n = blockIdx.x * 256 + t;
    if (n >= NN) return;
    float4* hp = (float4*)&g_h0[(size_t)n * HIDC];
    if (n < NPRO) {
        float f[INDIM];
        #pragma unroll
        for (int d = 0; d < INDIM; d++) f[d] = pf[(size_t)n * INDIM + d];
        #pragma unroll
        for (int q = 0; q < 8; q++) {
            float o[4];
            #pragma unroll
            for (int u = 0; u < 4; u++) {
                int c = q * 4 + u;
                float a = sb[c];
                #pragma unroll
                for (int d = 0; d < INDIM; d++) a = fmaf(f[d], sW[d * HIDC + c], a);
                o[u] = a;
            }
            hp[q] = make_float4(o[0], o[1], o[2], o[3]);
        }
    } else {
        #pragma unroll
        for (int q = 0; q < 8; q++)
            hp[q] = make_float4(shw[q * 4], shw[q * 4 + 1], shw[q * 4 + 2], shw[q * 4 + 3]);
    }
}

// ---------------- GEMM ----------------
template<int K, bool RELU, bool BIAS>
__global__ __launch_bounds__(256) void gemm_nc128(const float* __restrict__ A,
                                                  const float* __restrict__ W,
                                                  const float* __restrict__ bias,
                                                  float* __restrict__ C, int M) {
    __shared__ float sA[32][129];
    __shared__ float sW[32][128];
    int tid = threadIdx.x;
    int tx = tid & 15, ty = tid >> 4;
    int row0 = blockIdx.x * 128;
    float acc[8][8];
    #pragma unroll
    for (int i = 0; i < 8; i++)
        #pragma unroll
        for (int j = 0; j < 8; j++) acc[i][j] = 0.f;

    for (int kc = 0; kc < K; kc += 32) {
        for (int idx = tid; idx < 128 * 32; idx += 256) {
            int r = idx >> 5, k = idx & 31;
            int gr = row0 + r;
            sA[k][r] = (gr < M) ? A[(size_t)gr * K + kc + k] : 0.f;
        }
        for (int idx = tid; idx < 32 * 128; idx += 256) {
            int k = idx >> 7, c = idx & 127;
            sW[k][c] = W[(size_t)(kc + k) * 128 + c];
        }
        __syncthreads();
        #pragma unroll 4
        for (int k = 0; k < 32; k++) {
            float a[8], b[8];
            #pragma unroll
            for (int j = 0; j < 8; j++) { a[j] = sA[k][ty * 8 + j]; b[j] = sW[k][tx * 8 + j]; }
            #pragma unroll
            for (int i = 0; i < 8; i++)
                #pragma unroll
                for (int j = 0; j < 8; j++) acc[i][j] = fmaf(a[i], b[j], acc[i][j]);
        }
        __syncthreads();
    }
    #pragma unroll
    for (int i = 0; i < 8; i++) {
        int gr = row0 + ty * 8 + i;
        if (gr < M) {
            #pragma unroll
            for (int j = 0; j < 8; j++) {
                float v = acc[i][j];
                if (BIAS) v += bias[tx * 8 + j];
                if (RELU) v = fmaxf(v, 0.f);
                C[(size_t)gr * 128 + tx * 8 + j] = v;
            }
        }
    }
}

// ---------------- asd ----------------
template<int K>
__global__ void asd_kernel(const float* __restrict__ h, int foldoff, int M) {
    __shared__ float sf[K * 8];
    __shared__ float sh[32][K];
    int t = threadIdx.x;
    for (int i = t; i < K * 8; i += 256) sf[i] = g_fold[foldoff + i];
    int n0 = blockIdx.x * 32;
    for (int i = t; i < 32 * K; i += 256) {
        int r = i / K, k = i % K;
        int gn = n0 + r;
        sh[r][k] = (gn < M) ? h[(size_t)gn * K + k] : 0.f;
    }
    __syncthreads();
    int r = t >> 3, j = t & 7;
    int gn = n0 + r;
    if (gn < M) {
        float a = 0.f;
        #pragma unroll
        for (int k = 0; k < K; k++) a = fmaf(sh[r][k], sf[k * 8 + j], a);
        g_asd[gn * 8 + j] = a;
    }
}

// ---------------- agg ----------------
__device__ __forceinline__ float sel4(float4 v, int h) {
    return (h & 2) ? ((h & 1) ? v.w : v.z) : ((h & 1) ? v.y : v.x);
}

__global__ __launch_bounds__(256) void agg_kernel(const float* __restrict__ x,
                                                  const float* __restrict__ bias,
                                                  float* __restrict__ hout,
                                                  int nbase, int ncount, int aeoff, int outbase) {
    __shared__ float4 exb[8][64];
    __shared__ int    srcb[8][64];
    int lane = threadIdx.x & 31, w = threadIdx.x >> 5;
    int n = nbase + blockIdx.x * 8 + w;
    if (n >= nbase + ncount) return;
    int off = g_rowptr[n];
    int deg = g_rowptr[n + 1] - off;
    const float4 ad = *(const float4*)&g_asd[n * 8 + 4];

    float4 m = make_float4(-1e30f, -1e30f, -1e30f, -1e30f);
    for (int i = lane; i < deg; i += 32) {
        int s = g_csr_src[off + i];
        float4 ae = *(const float4*)&g_csr_ae[(size_t)(off + i) * 8 + aeoff];
        float4 as = *(const float4*)&g_asd[s * 8];
        float4 al;
        al.x = lrelu(as.x + ad.x + ae.x);
        al.y = lrelu(as.y + ad.y + ae.y);
        al.z = lrelu(as.z + ad.z + ae.z);
        al.w = lrelu(as.w + ad.w + ae.w);
        m.x = fmaxf(m.x, al.x); m.y = fmaxf(m.y, al.y);
        m.z = fmaxf(m.z, al.z); m.w = fmaxf(m.w, al.w);
        if (i < 64) { exb[w][i] = al; srcb[w][i] = s; }
    }
    #pragma unroll
    for (int o = 16; o; o >>= 1) {
        m.x = fmaxf(m.x, __shfl_xor_sync(0xffffffffu, m.x, o));
        m.y = fmaxf(m.y, __shfl_xor_sync(0xffffffffu, m.y, o));
        m.z = fmaxf(m.z, __shfl_xor_sync(0xffffffffu, m.z, o));
        m.w = fmaxf(m.w, __shfl_xor_sync(0xffffffffu, m.w, o));
    }

    float4 den = make_float4(0.f, 0.f, 0.f, 0.f);
    for (int i = lane; i < deg; i += 32) {
        float4 al;
        if (i < 64) al = exb[w][i];
        else {
            int s = g_csr_src[off + i];
            float4 ae = *(const float4*)&g_csr_ae[(size_t)(off + i) * 8 + aeoff];
            float4 as = *(const float4*)&g_asd[s * 8];
            al.x = lrelu(as.x + ad.x + ae.x); al.y = lrelu(as.y + ad.y + ae.y);
            al.z = lrelu(as.z + ad.z + ae.z); al.w = lrelu(as.w + ad.w + ae.w);
        }
        float4 ex;
        ex.x = __expf(al.x - m.x); ex.y = __expf(al.y - m.y);
        ex.z = __expf(al.z - m.z); ex.w = __expf(al.w - m.w);
        den.x += ex.x; den.y += ex.y; den.z += ex.z; den.w += ex.w;
        if (i < 64) exb[w][i] = ex;
    }
    #pragma unroll
    for (int o = 16; o; o >>= 1) {
        den.x += __shfl_xor_sync(0xffffffffu, den.x, o);
        den.y += __shfl_xor_sync(0xffffffffu, den.y, o);
        den.z += __shfl_xor_sync(0xffffffffu, den.z, o);
        den.w += __shfl_xor_sync(0xffffffffu, den.w, o);
    }
    __syncwarp();

    int hl = lane >> 3;
    float dh = sel4(den, hl);
    float mh = sel4(m, hl);
    float inv = 1.f / (dh + 1e-16f);
    float4 acc = make_float4(0.f, 0.f, 0.f, 0.f);
    for (int i = 0; i < deg; i++) {
        float exh; int s;
        if (i < 64) {
            float4 e4 = exb[w][i];
            exh = sel4(e4, hl);
            s = srcb[w][i];
        } else {
            s = g_csr_src[off + i];
            float4 ae = *(const float4*)&g_csr_ae[(size_t)(off + i) * 8 + aeoff];
            float4 as = *(const float4*)&g_asd[s * 8];
            float4 al;
            al.x = lrelu(as.x + ad.x + ae.x); al.y = lrelu(as.y + ad.y + ae.y);
            al.z = lrelu(as.z + ad.z + ae.z); al.w = lrelu(as.w + ad.w + ae.w);
            exh = __expf(sel4(al, hl) - mh);
        }
        const float4 xv = *(const float4*)&x[(size_t)s * HC + lane * 4];
        acc.x = fmaf(exh, xv.x, acc.x);
        acc.y = fmaf(exh, xv.y, acc.y);
        acc.z = fmaf(exh, xv.z, acc.z);
        acc.w = fmaf(exh, xv.w, acc.w);
    }
    float4 b4 = *(const float4*)&bias[lane * 4];
    float4 r;
    r.x = fmaf(acc.x, inv, b4.x);
    r.y = fmaf(acc.y, inv, b4.y);
    r.z = fmaf(acc.z, inv, b4.z);
    r.w = fmaf(acc.w, inv, b4.w);
    r.x = r.x > 0.f ? r.x : expm1f(r.x);
    r.y = r.y > 0.f ? r.y : expm1f(r.y);
    r.z = r.z > 0.f ? r.z : expm1f(r.z);
    r.w = r.w > 0.f ? r.w : expm1f(r.w);
    *(float4*)&hout[(size_t)(n - outbase) * HC + lane * 4] = r;
}

// ---------------- mlp2 ----------------
__global__ void mlp2_kernel(const float* __restrict__ hid, const float* __restrict__ Wm2,
                            const float* __restrict__ bm2, float* __restrict__ out) {
    __shared__ float sW[FFH * ODIM];
    __shared__ float sb[ODIM];
    int t = threadIdx.x;
    if (t < FFH * ODIM) sW[t] = Wm2[t];
    if (t < ODIM) sb[t] = bm2[t];
    __syncthreads();
    int n = blockIdx.x * 256 + t;
    if (n >= NWAT) return;
    float a0 = sb[0], a1 = sb[1];
    #pragma unroll 4
    for (int k = 0; k < FFH; k++) {
        float v = hid[(size_t)n * FFH + k];
        a0 = fmaf(v, sW[2 * k], a0);
        a1 = fmaf(v, sW[2 * k + 1], a1);
    }
    out[n * 2] = a0;
    out[n * 2 + 1] = a1;
}

// ---------------- launch ----------------
extern "C" void kernel_launch(void* const* d_in, const int* in_sizes, int n_in,
                              void* d_out, int out_size) {
    // Resolve REAL device addresses of __device__ globals (host symbol name is
    // the host shadow — on GB300/ATS that silently reads/writes host memory!).
    static float *p_h0 = nullptr, *p_x = nullptr, *p_h1 = nullptr, *p_h2 = nullptr;
    if (!p_h0) {
        cudaGetSymbolAddress((void**)&p_h0, g_h0);
        cudaGetSymbolAddress((void**)&p_x,  g_x);
        cudaGetSymbolAddress((void**)&p_h1, g_h1);
        cudaGetSymbolAddress((void**)&p_h2, g_h2);
    }

    const float* ppos  = (const float*)d_in[0];
    const float* wpos  = (const float*)d_in[1];
    const float* pf    = (const float*)d_in[2];
    const int*   ei    = (const int*)d_in[3];   // int32 (confirmed)
    const float* gamma = (const float*)d_in[4];
    const float* Wf    = (const float*)d_in[5];
    const float* bf    = (const float*)d_in[6];
    const float* We    = (const float*)d_in[7];
    const float* be    = (const float*)d_in[8];
    const float* W1    = (const float*)d_in[9];
    const float* atts1 = (const float*)d_in[10];
    const float* attd1 = (const float*)d_in[11];
    const float* Wedge1= (const float*)d_in[12];
    const float* atte1 = (const float*)d_in[13];
    const float* b1    = (const float*)d_in[14];
    const float* W2    = (const float*)d_in[15];
    const float* atts2 = (const float*)d_in[16];
    const float* attd2 = (const float*)d_in[17];
    const float* Wedge2= (const float*)d_in[18];
    const float* atte2 = (const float*)d_in[19];
    const float* b2    = (const float*)d_in[20];
    const float* Wm1   = (const float*)d_in[21];
    const float* bm1   = (const float*)d_in[22];
    const float* Wm2   = (const float*)d_in[23];
    const float* bm2   = (const float*)d_in[24];
    float* out = (float*)d_out;

    const int EB = (EE + 255) / 256;
    const int NB = (NN + 255) / 256;
    const int SB = (NN + 1023) / 1024;

    fold_kernel<<<1, 256>>>(We, be, Wedge1, atte1, Wedge2, atte2,
                            W1, atts1, attd1, W2, atts2, attd2, Wf, bf);
    zero_kernel<<<NB, 256>>>();
    edge_prep<<<EB, 256>>>(ei, ppos, wpos, gamma);
    scan1_kernel<<<SB, 1024>>>();
    scan2_kernel<<<1, 1>>>(SB);
    scan3_kernel<<<NB, 256>>>();
    scatter_kernel<<<EB, 256>>>();
    h0_kernel<<<NB, 256>>>(pf, Wf, bf);

    // layer 1
    gemm_nc128<32, false, false><<<(NN + 127) / 128, 256>>>(p_h0, W1, nullptr, p_x, NN);
    asd_kernel<32><<<(NN + 31) / 32, 256>>>(p_h0, FOLD_ASD1, NN);
    agg_kernel<<<(NN + 7) / 8, 256>>>(p_x, b1, p_h1, 0, NN, 0, 0);

    // layer 2 (aggregate only water dst nodes)
    gemm_nc128<128, false, false><<<(NN + 127) / 128, 256>>>(p_h1, W2, nullptr, p_x, NN);
    asd_kernel<128><<<(NN + 31) / 32, 256>>>(p_h1, FOLD_ASD2, NN);
    agg_kernel<<<(NWAT + 7) / 8, 256>>>(p_x, b2, p_h2, NPRO, NWAT, 4, NPRO);

    // MLP on water nodes only
    gemm_nc128<128, true, true><<<(NWAT + 127) / 128, 256>>>(p_h2, Wm1, bm1, p_x, NWAT);
    mlp2_kernel<<<(NWAT + 255) / 256, 256>>>(p_x, Wm2, bm2, out);
}

// round 10
// speedup vs baseline: 1.0276x; 1.0276x over previous
#include <cuda_runtime.h>
#include <math.h>

// ---------------- problem constants ----------------
#define NPRO 60000
#define NWAT 40000
#define NN   100000
#define EE   1000000
#define INDIM 21
#define HIDC  32
#define HEADS 4
#define HC    128
#define EK    32
#define EDIM  32
#define FFH   128
#define ODIM  2
#define RADMAX 5.0f

#define FOLD_ME   0
#define FOLD_AEC  256
#define FOLD_ASD1 264
#define FOLD_ASD2 520
#define FOLD_HW   1544

// ---------------- static device scratch ----------------
__device__ int   g_csr_src[EE];
__device__ float g_csr_ae[EE * 8];
__device__ int   g_rowptr[NN + 1];
__device__ int   g_cnt[NN];
__device__ int   g_cur[NN];
__device__ int   g_bsum[128];
__device__ float g_h0[NN * HIDC];
__device__ float g_x[(size_t)NN * HC];
__device__ float g_h1[(size_t)NN * HC];
__device__ float g_h2[(size_t)NWAT * HC];
__device__ float g_asd[NN * 8];
__device__ float g_fold[2048];

__device__ __forceinline__ float lrelu(float x) { return fmaxf(x, 0.2f * x); }

// ---------------- fold kernel ----------------
__global__ void fold_kernel(const float* __restrict__ We,  const float* __restrict__ be,
                            const float* __restrict__ Wedge1, const float* __restrict__ atte1,
                            const float* __restrict__ Wedge2, const float* __restrict__ atte2,
                            const float* __restrict__ W1, const float* __restrict__ atts1, const float* __restrict__ attd1,
                            const float* __restrict__ W2, const float* __restrict__ atts2, const float* __restrict__ attd2,
                            const float* __restrict__ Wf, const float* __restrict__ bf) {
    __shared__ float Ve[2][EDIM][HEADS];
    int t = threadIdx.x;
    if (t < 256) {
        int l = t >> 7, r = t & 127, d = r >> 2, h = r & 3;
        const float* Wg = l ? Wedge2 : Wedge1;
        const float* ae = l ? atte2 : atte1;
        float s = 0.f;
        #pragma unroll
        for (int c = 0; c < 32; c++) s = fmaf(Wg[d * HC + h * 32 + c], ae[h * 32 + c], s);
        Ve[l][d][h] = s;
    }
    __syncthreads();
    if (t < 256) {
        int k = t >> 3, j = t & 7, l = j >> 2, h = j & 3;
        float s = 0.f;
        #pragma unroll
        for (int d = 0; d < 32; d++) s = fmaf(We[k * 32 + d], Ve[l][d][h], s);
        g_fold[FOLD_ME + k * 8 + j] = s;
    }
    if (t < 8) {
        int l = t >> 2, h = t & 3;
        float s = 0.f;
        for (int d = 0; d < 32; d++) s = fmaf(be[d], Ve[l][d][h], s);
        g_fold[FOLD_AEC + t] = s;
    }
    if (t < 256) {
        int d = t >> 3, j = t & 7, h = j & 3;
        const float* att = (j < 4) ? atts1 : attd1;
        float s = 0.f;
        #pragma unroll
        for (int c = 0; c < 32; c++) s = fmaf(W1[d * HC + h * 32 + c], att[h * 32 + c], s);
        g_fold[FOLD_ASD1 + d * 8 + j] = s;
    }
    for (int i = t; i < 1024; i += 256) {
        int d = i >> 3, j = i & 7, h = j & 3;
        const float* att = (j < 4) ? atts2 : attd2;
        float s = 0.f;
        #pragma unroll
        for (int c = 0; c < 32; c++) s = fmaf(W2[d * HC + h * 32 + c], att[h * 32 + c], s);
        g_fold[FOLD_ASD2 + i] = s;
    }
    if (t < 32) g_fold[FOLD_HW + t] = Wf[(INDIM - 1) * HIDC + t] + bf[t];
}

__global__ void zero_kernel() {
    int i = blockIdx.x * 256 + threadIdx.x;
    if (i < NN) { g_cnt[i] = 0; g_cur[i] = 0; }
}

// ---------------- pass A: degree count only (reads dst row of edge_index) ----------------
__global__ void count_kernel(const int* __restrict__ ei) {
    int e = blockIdx.x * 256 + threadIdx.x;
    if (e >= EE) return;
    int d = ei[EE + e];
    if ((unsigned)d >= NN) d = 0;
    atomicAdd(&g_cnt[d], 1);
}

// ---------------- scan ----------------
__global__ void scan1_kernel() {
    __shared__ int sm[1024];
    int tid = threadIdx.x;
    int i = blockIdx.x * 1024 + tid;
    int v = (i < NN) ? g_cnt[i] : 0;
    sm[tid] = v;
    __syncthreads();
    for (int off = 1; off < 1024; off <<= 1) {
        int t = (tid >= off) ? sm[tid - off] : 0;
        __syncthreads();
        sm[tid] += t;
        __syncthreads();
    }
    if (i < NN) g_rowptr[i] = sm[tid] - v;
    if (tid == 1023) g_bsum[blockIdx.x] = sm[1023];
}
__global__ void scan2_kernel(int nb) {
    int run = 0;
    for (int b = 0; b < nb; b++) { int v = g_bsum[b]; g_bsum[b] = run; run += v; }
    g_rowptr[NN] = run;
}
__global__ void scan3_kernel() {
    int i = blockIdx.x * 256 + threadIdx.x;
    if (i < NN) g_rowptr[i] += g_bsum[i >> 10];
}

// ---------------- pass B: fused edge-attr compute + direct CSR scatter ----------------
__global__ void edge_scatter(const int* __restrict__ ei,
                             const float* __restrict__ ppos, const float* __restrict__ wpos,
                             const float* __restrict__ gamma) {
    __shared__ float sMe[256];
    __shared__ float sAec[8];
    int t = threadIdx.x;
    if (t < 256) sMe[t] = g_fold[FOLD_ME + t];
    if (t < 8)   sAec[t] = g_fold[FOLD_AEC + t];
    __syncthreads();
    int e = blockIdx.x * 256 + t;
    if (e >= EE) return;
    int s = ei[e];
    int d = ei[EE + e];
    if ((unsigned)s >= NN) s = 0;
    if ((unsigned)d >= NN) d = 0;
    const float* ps = (s < NPRO) ? (ppos + 3 * s) : (wpos + 3 * (s - NPRO));
    const float* pd = (d < NPRO) ? (ppos + 3 * d) : (wpos + 3 * (d - NPRO));
    float dx = pd[0] - ps[0], dy = pd[1] - ps[1], dz = pd[2] - ps[2];
    float dis = sqrtf(dx * dx + dy * dy + dz * dz);
    float g = gamma[0];
    float acc[8];
    #pragma unroll
    for (int j = 0; j < 8; j++) acc[j] = sAec[j];
    #pragma unroll
    for (int k = 0; k < 32; k++) {
        float tt = dis - (float)k * (RADMAX / 31.0f);
        float r = __expf(-g * tt * tt);
        #pragma unroll
        for (int j = 0; j < 8; j++) acc[j] = fmaf(r, sMe[k * 8 + j], acc[j]);
    }
    int p = atomicAdd(&g_cur[d], 1);
    int idx = g_rowptr[d] + p;
    g_csr_src[idx] = s;
    float4* dp = (float4*)&g_csr_ae[(size_t)idx * 8];
    dp[0] = make_float4(acc[0], acc[1], acc[2], acc[3]);
    dp[1] = make_float4(acc[4], acc[5], acc[6], acc[7]);
}

// ---------------- h0 ----------------
__global__ void h0_kernel(const float* __restrict__ pf, const float* __restrict__ Wf,
                          const float* __restrict__ bf) {
    __shared__ float sW[INDIM * HIDC];
    __shared__ float sb[HIDC];
    __shared__ float shw[HIDC];
    int t = threadIdx.x;
    for (int i = t; i < INDIM * HIDC; i += 256) sW[i] = Wf[i];
    if (t < HIDC) { sb[t] = bf[t]; shw[t] = g_fold[FOLD_HW + t]; }
    __syncthreads();
    int n = blockIdx.x * 256 + t;
    if (n >= NN) return;
    float4* hp = (float4*)&g_h0[(size_t)n * HIDC];
    if (n < NPRO) {
        float f[INDIM];
        #pragma unroll
        for (int d = 0; d < INDIM; d++) f[d] = pf[(size_t)n * INDIM + d];
        #pragma unroll
        for (int q = 0; q < 8; q++) {
            float o[4];
            #pragma unroll
            for (int u = 0; u < 4; u++) {
                int c = q * 4 + u;
                float a = sb[c];
                #pragma unroll
                for (int d = 0; d < INDIM; d++) a = fmaf(f[d], sW[d * HIDC + c], a);
                o[u] = a;
            }
            hp[q] = make_float4(o[0], o[1], o[2], o[3]);
        }
    } else {
        #pragma unroll
        for (int q = 0; q < 8; q++)
            hp[q] = make_float4(shw[q * 4], shw[q * 4 + 1], shw[q * 4 + 2], shw[q * 4 + 3]);
    }
}

// ---------------- GEMM ----------------
template<int K, bool RELU, bool BIAS>
__global__ __launch_bounds__(256) void gemm_nc128(const float* __restrict__ A,
                                                  const float* __restrict__ W,
                                                  const float* __restrict__ bias,
                                                  float* __restrict__ C, int M) {
    __shared__ float sA[32][129];
    __shared__ float sW[32][128];
    int tid = threadIdx.x;
    int tx = tid & 15, ty = tid >> 4;
    int row0 = blockIdx.x * 128;
    float acc[8][8];
    #pragma unroll
    for (int i = 0; i < 8; i++)
        #pragma unroll
        for (int j = 0; j < 8; j++) acc[i][j] = 0.f;

    for (int kc = 0; kc < K; kc += 32) {
        for (int idx = tid; idx < 128 * 32; idx += 256) {
            int r = idx >> 5, k = idx & 31;
            int gr = row0 + r;
            sA[k][r] = (gr < M) ? A[(size_t)gr * K + kc + k] : 0.f;
        }
        for (int idx = tid; idx < 32 * 128; idx += 256) {
            int k = idx >> 7, c = idx & 127;
            sW[k][c] = W[(size_t)(kc + k) * 128 + c];
        }
        __syncthreads();
        #pragma unroll 4
        for (int k = 0; k < 32; k++) {
            float a[8], b[8];
            #pragma unroll
            for (int j = 0; j < 8; j++) { a[j] = sA[k][ty * 8 + j]; b[j] = sW[k][tx * 8 + j]; }
            #pragma unroll
            for (int i = 0; i < 8; i++)
                #pragma unroll
                for (int j = 0; j < 8; j++) acc[i][j] = fmaf(a[i], b[j], acc[i][j]);
        }
        __syncthreads();
    }
    #pragma unroll
    for (int i = 0; i < 8; i++) {
        int gr = row0 + ty * 8 + i;
        if (gr < M) {
            #pragma unroll
            for (int j = 0; j < 8; j++) {
                float v = acc[i][j];
                if (BIAS) v += bias[tx * 8 + j];
                if (RELU) v = fmaxf(v, 0.f);
                C[(size_t)gr * 128 + tx * 8 + j] = v;
            }
        }
    }
}

// ---------------- asd ----------------
template<int K>
__global__ void asd_kernel(const float* __restrict__ h, int foldoff, int M) {
    __shared__ float sf[K * 8];
    __shared__ float sh[32][K];
    int t = threadIdx.x;
    for (int i = t; i < K * 8; i += 256) sf[i] = g_fold[foldoff + i];
    int n0 = blockIdx.x * 32;
    for (int i = t; i < 32 * K; i += 256) {
        int r = i / K, k = i % K;
        int gn = n0 + r;
        sh[r][k] = (gn < M) ? h[(size_t)gn * K + k] : 0.f;
    }
    __syncthreads();
    int r = t >> 3, j = t & 7;
    int gn = n0 + r;
    if (gn < M) {
        float a = 0.f;
        #pragma unroll
        for (int k = 0; k < K; k++) a = fmaf(sh[r][k], sf[k * 8 + j], a);
        g_asd[gn * 8 + j] = a;
    }
}

// ---------------- agg ----------------
__device__ __forceinline__ float sel4(float4 v, int h) {
    return (h & 2) ? ((h & 1) ? v.w : v.z) : ((h & 1) ? v.y : v.x);
}

__global__ __launch_bounds__(256) void agg_kernel(const float* __restrict__ x,
                                                  const float* __restrict__ bias,
                                                  float* __restrict__ hout,
                                                  int nbase, int ncount, int aeoff, int outbase) {
    __shared__ float4 exb[8][64];
    __shared__ int    srcb[8][64];
    int lane = threadIdx.x & 31, w = threadIdx.x >> 5;
    int n = nbase + blockIdx.x * 8 + w;
    if (n >= nbase + ncount) return;
    int off = g_rowptr[n];
    int deg = g_rowptr[n + 1] - off;
    const float4 ad = *(const float4*)&g_asd[n * 8 + 4];

    float4 m = make_float4(-1e30f, -1e30f, -1e30f, -1e30f);
    for (int i = lane; i < deg; i += 32) {
        int s = g_csr_src[off + i];
        float4 ae = *(const float4*)&g_csr_ae[(size_t)(off + i) * 8 + aeoff];
        float4 as = *(const float4*)&g_asd[s * 8];
        float4 al;
        al.x = lrelu(as.x + ad.x + ae.x);
        al.y = lrelu(as.y + ad.y + ae.y);
        al.z = lrelu(as.z + ad.z + ae.z);
        al.w = lrelu(as.w + ad.w + ae.w);
        m.x = fmaxf(m.x, al.x); m.y = fmaxf(m.y, al.y);
        m.z = fmaxf(m.z, al.z); m.w = fmaxf(m.w, al.w);
        if (i < 64) { exb[w][i] = al; srcb[w][i] = s; }
    }
    #pragma unroll
    for (int o = 16; o; o >>= 1) {
        m.x = fmaxf(m.x, __shfl_xor_sync(0xffffffffu, m.x, o));
        m.y = fmaxf(m.y, __shfl_xor_sync(0xffffffffu, m.y, o));
        m.z = fmaxf(m.z, __shfl_xor_sync(0xffffffffu, m.z, o));
        m.w = fmaxf(m.w, __shfl_xor_sync(0xffffffffu, m.w, o));
    }

    float4 den = make_float4(0.f, 0.f, 0.f, 0.f);
    for (int i = lane; i < deg; i += 32) {
        float4 al;
        if (i < 64) al = exb[w][i];
        else {
            int s = g_csr_src[off + i];
            float4 ae = *(const float4*)&g_csr_ae[(size_t)(off + i) * 8 + aeoff];
            float4 as = *(const float4*)&g_asd[s * 8];
            al.x = lrelu(as.x + ad.x + ae.x); al.y = lrelu(as.y + ad.y + ae.y);
            al.z = lrelu(as.z + ad.z + ae.z); al.w = lrelu(as.w + ad.w + ae.w);
        }
        float4 ex;
        ex.x = __expf(al.x - m.x); ex.y = __expf(al.y - m.y);
        ex.z = __expf(al.z - m.z); ex.w = __expf(al.w - m.w);
        den.x += ex.x; den.y += ex.y; den.z += ex.z; den.w += ex.w;
        if (i < 64) exb[w][i] = ex;
    }
    #pragma unroll
    for (int o = 16; o; o >>= 1) {
        den.x += __shfl_xor_sync(0xffffffffu, den.x, o);
        den.y += __shfl_xor_sync(0xffffffffu, den.y, o);
        den.z += __shfl_xor_sync(0xffffffffu, den.z, o);
        den.w += __shfl_xor_sync(0xffffffffu, den.w, o);
    }
    __syncwarp();

    int hl = lane >> 3;
    float dh = sel4(den, hl);
    float mh = sel4(m, hl);
    float inv = 1.f / (dh + 1e-16f);
    float4 acc = make_float4(0.f, 0.f, 0.f, 0.f);
    for (int i = 0; i < deg; i++) {
        float exh; int s;
        if (i < 64) {
            float4 e4 = exb[w][i];
            exh = sel4(e4, hl);
            s = srcb[w][i];
        } else {
            s = g_csr_src[off + i];
            float4 ae = *(const float4*)&g_csr_ae[(size_t)(off + i) * 8 + aeoff];
            float4 as = *(const float4*)&g_asd[s * 8];
            float4 al;
            al.x = lrelu(as.x + ad.x + ae.x); al.y = lrelu(as.y + ad.y + ae.y);
            al.z = lrelu(as.z + ad.z + ae.z); al.w = lrelu(as.w + ad.w + ae.w);
            exh = __expf(sel4(al, hl) - mh);
        }
        const float4 xv = *(const float4*)&x[(size_t)s * HC + lane * 4];
        acc.x = fmaf(exh, xv.x, acc.x);
        acc.y = fmaf(exh, xv.y, acc.y);
        acc.z = fmaf(exh, xv.z, acc.z);
        acc.w = fmaf(exh, xv.w, acc.w);
    }
    float4 b4 = *(const float4*)&bias[lane * 4];
    float4 r;
    r.x = fmaf(acc.x, inv, b4.x);
    r.y = fmaf(acc.y, inv, b4.y);
    r.z = fmaf(acc.z, inv, b4.z);
    r.w = fmaf(acc.w, inv, b4.w);
    r.x = r.x > 0.f ? r.x : expm1f(r.x);
    r.y = r.y > 0.f ? r.y : expm1f(r.y);
    r.z = r.z > 0.f ? r.z : expm1f(r.z);
    r.w = r.w > 0.f ? r.w : expm1f(r.w);
    *(float4*)&hout[(size_t)(n - outbase) * HC + lane * 4] = r;
}

// ---------------- mlp2 ----------------
__global__ void mlp2_kernel(const float* __restrict__ hid, const float* __restrict__ Wm2,
                            const float* __restrict__ bm2, float* __restrict__ out) {
    __shared__ float sW[FFH * ODIM];
    __shared__ float sb[ODIM];
    int t = threadIdx.x;
    if (t < FFH * ODIM) sW[t] = Wm2[t];
    if (t < ODIM) sb[t] = bm2[t];
    __syncthreads();
    int n = blockIdx.x * 256 + t;
    if (n >= NWAT) return;
    float a0 = sb[0], a1 = sb[1];
    #pragma unroll 4
    for (int k = 0; k < FFH; k++) {
        float v = hid[(size_t)n * FFH + k];
        a0 = fmaf(v, sW[2 * k], a0);
        a1 = fmaf(v, sW[2 * k + 1], a1);
    }
    out[n * 2] = a0;
    out[n * 2 + 1] = a1;
}

// ---------------- launch ----------------
extern "C" void kernel_launch(void* const* d_in, const int* in_sizes, int n_in,
                              void* d_out, int out_size) {
    static float *p_h0 = nullptr, *p_x = nullptr, *p_h1 = nullptr, *p_h2 = nullptr;
    if (!p_h0) {
        cudaGetSymbolAddress((void**)&p_h0, g_h0);
        cudaGetSymbolAddress((void**)&p_x,  g_x);
        cudaGetSymbolAddress((void**)&p_h1, g_h1);
        cudaGetSymbolAddress((void**)&p_h2, g_h2);
    }

    const float* ppos  = (const float*)d_in[0];
    const float* wpos  = (const float*)d_in[1];
    const float* pf    = (const float*)d_in[2];
    const int*   ei    = (const int*)d_in[3];
    const float* gamma = (const float*)d_in[4];
    const float* Wf    = (const float*)d_in[5];
    const float* bf    = (const float*)d_in[6];
    const float* We    = (const float*)d_in[7];
    const float* be    = (const float*)d_in[8];
    const float* W1    = (const float*)d_in[9];
    const float* atts1 = (const float*)d_in[10];
    const float* attd1 = (const float*)d_in[11];
    const float* Wedge1= (const float*)d_in[12];
    const float* atte1 = (const float*)d_in[13];
    const float* b1    = (const float*)d_in[14];
    const float* W2    = (const float*)d_in[15];
    const float* atts2 = (const float*)d_in[16];
    const float* attd2 = (const float*)d_in[17];
    const float* Wedge2= (const float*)d_in[18];
    const float* atte2 = (const float*)d_in[19];
    const float* b2    = (const float*)d_in[20];
    const float* Wm1   = (const float*)d_in[21];
    const float* bm1   = (const float*)d_in[22];
    const float* Wm2   = (const float*)d_in[23];
    const float* bm2   = (const float*)d_in[24];
    float* out = (float*)d_out;

    const int EB = (EE + 255) / 256;
    const int NB = (NN + 255) / 256;
    const int SB = (NN + 1023) / 1024;

    fold_kernel<<<1, 256>>>(We, be, Wedge1, atte1, Wedge2, atte2,
                            W1, atts1, attd1, W2, atts2, attd2, Wf, bf);
    zero_kernel<<<NB, 256>>>();
    count_kernel<<<EB, 256>>>(ei);
    scan1_kernel<<<SB, 1024>>>();
    scan2_kernel<<<1, 1>>>(SB);
    scan3_kernel<<<NB, 256>>>();
    edge_scatter<<<EB, 256>>>(ei, ppos, wpos, gamma);
    h0_kernel<<<NB, 256>>>(pf, Wf, bf);

    // layer 1
    gemm_nc128<32, false, false><<<(NN + 127) / 128, 256>>>(p_h0, W1, nullptr, p_x, NN);
    asd_kernel<32><<<(NN + 31) / 32, 256>>>(p_h0, FOLD_ASD1, NN);
    agg_kernel<<<(NN + 7) / 8, 256>>>(p_x, b1, p_h1, 0, NN, 0, 0);

    // layer 2 (aggregate only water dst nodes)
    gemm_nc128<128, false, false><<<(NN + 127) / 128, 256>>>(p_h1, W2, nullptr, p_x, NN);
    asd_kernel<128><<<(NN + 31) / 32, 256>>>(p_h1, FOLD_ASD2, NN);
    agg_kernel<<<(NWAT + 7) / 8, 256>>>(p_x, b2, p_h2, NPRO, NWAT, 4, NPRO);

    // MLP on water nodes only
    gemm_nc128<128, true, true><<<(NWAT + 127) / 128, 256>>>(p_h2, Wm1, bm1, p_x, NWAT);
    mlp2_kernel<<<(NWAT + 255) / 256, 256>>>(p_x, Wm2, bm2, out);
}

// round 11
// speedup vs baseline: 1.0856x; 1.0565x over previous
#include <cuda_runtime.h>
#include <math.h>

// ---------------- problem constants ----------------
#define NPRO 60000
#define NWAT 40000
#define NN   100000
#define EE   1000000
#define INDIM 21
#define HIDC  32
#define HEADS 4
#define HC    128
#define EK    32
#define EDIM  32
#define FFH   128
#define ODIM  2
#define RADMAX 5.0f

#define FOLD_ME   0      // 32*8
#define FOLD_AEC  256    // 8
#define FOLD_ASD1 264    // 32*8 (intermediate for W1C)
#define FOLD_ASD2 520    // 128*8
#define FOLD_W1C  1544   // 21*136 : cols 0..127 = Wf@W1, cols 128..135 = Wf@ASD1
#define FOLD_C1   4400   // 136    : bf@W1 || bf@ASD1

// ---------------- static device scratch ----------------
__device__ int   g_csr_src[EE];
__device__ float g_csr_ae[EE * 8];
__device__ int   g_rowptr[NN + 1];
__device__ int   g_cnt[NN];
__device__ int   g_cur[NN];
__device__ int   g_bsum[128];
__device__ float g_x[(size_t)NN * HC];
__device__ float g_h1[(size_t)NN * HC];
__device__ float g_h2[(size_t)NWAT * HC];
__device__ float g_asd[NN * 8];
__device__ float g_fold[8192];

__device__ __forceinline__ float lrelu(float x) { return fmaxf(x, 0.2f * x); }

// ---------------- fold kernel ----------------
__global__ void fold_kernel(const float* __restrict__ We,  const float* __restrict__ be,
                            const float* __restrict__ Wedge1, const float* __restrict__ atte1,
                            const float* __restrict__ Wedge2, const float* __restrict__ atte2,
                            const float* __restrict__ W1, const float* __restrict__ atts1, const float* __restrict__ attd1,
                            const float* __restrict__ W2, const float* __restrict__ atts2, const float* __restrict__ attd2,
                            const float* __restrict__ Wf, const float* __restrict__ bf) {
    __shared__ float Ve[2][EDIM][HEADS];
    int t = threadIdx.x;
    if (t < 256) {
        int l = t >> 7, r = t & 127, d = r >> 2, h = r & 3;
        const float* Wg = l ? Wedge2 : Wedge1;
        const float* ae = l ? atte2 : atte1;
        float s = 0.f;
        #pragma unroll
        for (int c = 0; c < 32; c++) s = fmaf(Wg[d * HC + h * 32 + c], ae[h * 32 + c], s);
        Ve[l][d][h] = s;
    }
    __syncthreads();
    if (t < 256) {
        int k = t >> 3, j = t & 7, l = j >> 2, h = j & 3;
        float s = 0.f;
        #pragma unroll
        for (int d = 0; d < 32; d++) s = fmaf(We[k * 32 + d], Ve[l][d][h], s);
        g_fold[FOLD_ME + k * 8 + j] = s;
    }
    if (t < 8) {
        int l = t >> 2, h = t & 3;
        float s = 0.f;
        for (int d = 0; d < 32; d++) s = fmaf(be[d], Ve[l][d][h], s);
        g_fold[FOLD_AEC + t] = s;
    }
    if (t < 256) {   // ASD1[k][j], k<32 (h0 dims)
        int d = t >> 3, j = t & 7, h = j & 3;
        const float* att = (j < 4) ? atts1 : attd1;
        float s = 0.f;
        #pragma unroll
        for (int c = 0; c < 32; c++) s = fmaf(W1[d * HC + h * 32 + c], att[h * 32 + c], s);
        g_fold[FOLD_ASD1 + d * 8 + j] = s;
    }
    for (int i = t; i < 1024; i += 256) {
        int d = i >> 3, j = i & 7, h = j & 3;
        const float* att = (j < 4) ? atts2 : attd2;
        float s = 0.f;
        #pragma unroll
        for (int c = 0; c < 32; c++) s = fmaf(W2[d * HC + h * 32 + c], att[h * 32 + c], s);
        g_fold[FOLD_ASD2 + i] = s;
    }
    __syncthreads();   // ASD1 visible to all threads in block

    // W1C[d][c] = sum_k Wf[d][k] * (c<128 ? W1[k][c] : ASD1[k][c-128])
    for (int i = t; i < INDIM * 136; i += 256) {
        int d = i / 136, c = i % 136;
        float s = 0.f;
        if (c < 128) {
            #pragma unroll
            for (int k = 0; k < 32; k++) s = fmaf(Wf[d * 32 + k], W1[k * 128 + c], s);
        } else {
            int j = c - 128;
            #pragma unroll
            for (int k = 0; k < 32; k++) s = fmaf(Wf[d * 32 + k], g_fold[FOLD_ASD1 + k * 8 + j], s);
        }
        g_fold[FOLD_W1C + i] = s;
    }
    // C1[c] = sum_k bf[k] * (c<128 ? W1[k][c] : ASD1[k][c-128])
    for (int i = t; i < 136; i += 256) {
        float s = 0.f;
        if (i < 128) {
            #pragma unroll
            for (int k = 0; k < 32; k++) s = fmaf(bf[k], W1[k * 128 + i], s);
        } else {
            int j = i - 128;
            #pragma unroll
            for (int k = 0; k < 32; k++) s = fmaf(bf[k], g_fold[FOLD_ASD1 + k * 8 + j], s);
        }
        g_fold[FOLD_C1 + i] = s;
    }
}

__global__ void zero_kernel() {
    int i = blockIdx.x * 256 + threadIdx.x;
    if (i < NN) { g_cnt[i] = 0; g_cur[i] = 0; }
}

// ---------------- pass A: degree count ----------------
__global__ void count_kernel(const int* __restrict__ ei) {
    int e = blockIdx.x * 256 + threadIdx.x;
    if (e >= EE) return;
    int d = ei[EE + e];
    if ((unsigned)d >= NN) d = 0;
    atomicAdd(&g_cnt[d], 1);
}

// ---------------- scan ----------------
__global__ void scan1_kernel() {
    __shared__ int sm[1024];
    int tid = threadIdx.x;
    int i = blockIdx.x * 1024 + tid;
    int v = (i < NN) ? g_cnt[i] : 0;
    sm[tid] = v;
    __syncthreads();
    for (int off = 1; off < 1024; off <<= 1) {
        int t = (tid >= off) ? sm[tid - off] : 0;
        __syncthreads();
        sm[tid] += t;
        __syncthreads();
    }
    if (i < NN) g_rowptr[i] = sm[tid] - v;
    if (tid == 1023) g_bsum[blockIdx.x] = sm[1023];
}
__global__ void scan2_kernel(int nb) {
    int run = 0;
    for (int b = 0; b < nb; b++) { int v = g_bsum[b]; g_bsum[b] = run; run += v; }
    g_rowptr[NN] = run;
}
__global__ void scan3_kernel() {
    int i = blockIdx.x * 256 + threadIdx.x;
    if (i < NN) g_rowptr[i] += g_bsum[i >> 10];
}

// ---------------- pass B: fused edge-attr compute + direct CSR scatter ----------------
__global__ void edge_scatter(const int* __restrict__ ei,
                             const float* __restrict__ ppos, const float* __restrict__ wpos,
                             const float* __restrict__ gamma) {
    __shared__ float sMe[256];
    __shared__ float sAec[8];
    int t = threadIdx.x;
    if (t < 256) sMe[t] = g_fold[FOLD_ME + t];
    if (t < 8)   sAec[t] = g_fold[FOLD_AEC + t];
    __syncthreads();
    int e = blockIdx.x * 256 + t;
    if (e >= EE) return;
    int s = ei[e];
    int d = ei[EE + e];
    if ((unsigned)s >= NN) s = 0;
    if ((unsigned)d >= NN) d = 0;
    const float* ps = (s < NPRO) ? (ppos + 3 * s) : (wpos + 3 * (s - NPRO));
    const float* pd = (d < NPRO) ? (ppos + 3 * d) : (wpos + 3 * (d - NPRO));
    float dx = pd[0] - ps[0], dy = pd[1] - ps[1], dz = pd[2] - ps[2];
    float dis = sqrtf(dx * dx + dy * dy + dz * dz);
    float g = gamma[0];
    float acc[8];
    #pragma unroll
    for (int j = 0; j < 8; j++) acc[j] = sAec[j];
    #pragma unroll
    for (int k = 0; k < 32; k++) {
        float tt = dis - (float)k * (RADMAX / 31.0f);
        float r = __expf(-g * tt * tt);
        #pragma unroll
        for (int j = 0; j < 8; j++) acc[j] = fmaf(r, sMe[k * 8 + j], acc[j]);
    }
    int p = atomicAdd(&g_cur[d], 1);
    int idx = g_rowptr[d] + p;
    g_csr_src[idx] = s;
    float4* dp = (float4*)&g_csr_ae[(size_t)idx * 8];
    dp[0] = make_float4(acc[0], acc[1], acc[2], acc[3]);
    dp[1] = make_float4(acc[4], acc[5], acc[6], acc[7]);
}

// ---------------- fused node prep for layer 1: x = feats@W1C + C1, asd likewise ----------------
__global__ __launch_bounds__(256) void node1_kernel(const float* __restrict__ pf) {
    __shared__ float sW[INDIM * 136];
    __shared__ float sC[136];
    __shared__ float sWat[136];
    int t = threadIdx.x;
    for (int i = t; i < INDIM * 136; i += 256) sW[i] = g_fold[FOLD_W1C + i];
    for (int i = t; i < 136; i += 256) {
        float c = g_fold[FOLD_C1 + i];
        sC[i] = c;
        sWat[i] = c + g_fold[FOLD_W1C + (INDIM - 1) * 136 + i];   // water = const row
    }
    __syncthreads();
    int n = blockIdx.x * 256 + t;
    if (n >= NN) return;
    if (n < NPRO) {
        float f[INDIM];
        #pragma unroll
        for (int d = 0; d < INDIM; d++) f[d] = pf[(size_t)n * INDIM + d];
        #pragma unroll 4
        for (int q = 0; q < 32; q++) {
            float4 a = *(const float4*)&sC[q * 4];
            #pragma unroll
            for (int d = 0; d < INDIM; d++) {
                float4 w = *(const float4*)&sW[d * 136 + q * 4];
                a.x = fmaf(f[d], w.x, a.x);
                a.y = fmaf(f[d], w.y, a.y);
                a.z = fmaf(f[d], w.z, a.z);
                a.w = fmaf(f[d], w.w, a.w);
            }
            *(float4*)&g_x[(size_t)n * HC + q * 4] = a;
        }
        #pragma unroll
        for (int q = 0; q < 2; q++) {
            float4 a = *(const float4*)&sC[128 + q * 4];
            #pragma unroll
            for (int d = 0; d < INDIM; d++) {
                float4 w = *(const float4*)&sW[d * 136 + 128 + q * 4];
                a.x = fmaf(f[d], w.x, a.x);
                a.y = fmaf(f[d], w.y, a.y);
                a.z = fmaf(f[d], w.z, a.z);
                a.w = fmaf(f[d], w.w, a.w);
            }
            *(float4*)&g_asd[n * 8 + q * 4] = a;
        }
    } else {
        #pragma unroll 4
        for (int q = 0; q < 32; q++)
            *(float4*)&g_x[(size_t)n * HC + q * 4] = *(const float4*)&sWat[q * 4];
        #pragma unroll
        for (int q = 0; q < 2; q++)
            *(float4*)&g_asd[n * 8 + q * 4] = *(const float4*)&sWat[128 + q * 4];
    }
}

// ---------------- GEMM ----------------
template<int K, bool RELU, bool BIAS>
__global__ __launch_bounds__(256) void gemm_nc128(const float* __restrict__ A,
                                                  const float* __restrict__ W,
                                                  const float* __restrict__ bias,
                                                  float* __restrict__ C, int M) {
    __shared__ float sA[32][129];
    __shared__ float sW[32][128];
    int tid = threadIdx.x;
    int tx = tid & 15, ty = tid >> 4;
    int row0 = blockIdx.x * 128;
    float acc[8][8];
    #pragma unroll
    for (int i = 0; i < 8; i++)
        #pragma unroll
        for (int j = 0; j < 8; j++) acc[i][j] = 0.f;

    for (int kc = 0; kc < K; kc += 32) {
        for (int idx = tid; idx < 128 * 32; idx += 256) {
            int r = idx >> 5, k = idx & 31;
            int gr = row0 + r;
            sA[k][r] = (gr < M) ? A[(size_t)gr * K + kc + k] : 0.f;
        }
        for (int idx = tid; idx < 32 * 128; idx += 256) {
            int k = idx >> 7, c = idx & 127;
            sW[k][c] = W[(size_t)(kc + k) * 128 + c];
        }
        __syncthreads();
        #pragma unroll 4
        for (int k = 0; k < 32; k++) {
            float a[8], b[8];
            #pragma unroll
            for (int j = 0; j < 8; j++) { a[j] = sA[k][ty * 8 + j]; b[j] = sW[k][tx * 8 + j]; }
            #pragma unroll
            for (int i = 0; i < 8; i++)
                #pragma unroll
                for (int j = 0; j < 8; j++) acc[i][j] = fmaf(a[i], b[j], acc[i][j]);
        }
        __syncthreads();
    }
    #pragma unroll
    for (int i = 0; i < 8; i++) {
        int gr = row0 + ty * 8 + i;
        if (gr < M) {
            #pragma unroll
            for (int j = 0; j < 8; j++) {
                float v = acc[i][j];
                if (BIAS) v += bias[tx * 8 + j];
                if (RELU) v = fmaxf(v, 0.f);
                C[(size_t)gr * 128 + tx * 8 + j] = v;
            }
        }
    }
}

// ---------------- asd (layer 2) ----------------
template<int K>
__global__ void asd_kernel(const float* __restrict__ h, int foldoff, int M) {
    __shared__ float sf[K * 8];
    __shared__ float sh[32][K];
    int t = threadIdx.x;
    for (int i = t; i < K * 8; i += 256) sf[i] = g_fold[foldoff + i];
    int n0 = blockIdx.x * 32;
    for (int i = t; i < 32 * K; i += 256) {
        int r = i / K, k = i % K;
        int gn = n0 + r;
        sh[r][k] = (gn < M) ? h[(size_t)gn * K + k] : 0.f;
    }
    __syncthreads();
    int r = t >> 3, j = t & 7;
    int gn = n0 + r;
    if (gn < M) {
        float a = 0.f;
        #pragma unroll
        for (int k = 0; k < K; k++) a = fmaf(sh[r][k], sf[k * 8 + j], a);
        g_asd[gn * 8 + j] = a;
    }
}

// ---------------- agg ----------------
__device__ __forceinline__ float sel4(float4 v, int h) {
    return (h & 2) ? ((h & 1) ? v.w : v.z) : ((h & 1) ? v.y : v.x);
}

__global__ __launch_bounds__(256) void agg_kernel(const float* __restrict__ x,
                                                  const float* __restrict__ bias,
                                                  float* __restrict__ hout,
                                                  int nbase, int ncount, int aeoff, int outbase) {
    __shared__ float4 exb[8][64];
    __shared__ int    srcb[8][64];
    int lane = threadIdx.x & 31, w = threadIdx.x >> 5;
    int n = nbase + blockIdx.x * 8 + w;
    if (n >= nbase + ncount) return;
    int off = g_rowptr[n];
    int deg = g_rowptr[n + 1] - off;
    const float4 ad = *(const float4*)&g_asd[n * 8 + 4];

    float4 m = make_float4(-1e30f, -1e30f, -1e30f, -1e30f);
    for (int i = lane; i < deg; i += 32) {
        int s = g_csr_src[off + i];
        float4 ae = *(const float4*)&g_csr_ae[(size_t)(off + i) * 8 + aeoff];
        float4 as = *(const float4*)&g_asd[s * 8];
        float4 al;
        al.x = lrelu(as.x + ad.x + ae.x);
        al.y = lrelu(as.y + ad.y + ae.y);
        al.z = lrelu(as.z + ad.z + ae.z);
        al.w = lrelu(as.w + ad.w + ae.w);
        m.x = fmaxf(m.x, al.x); m.y = fmaxf(m.y, al.y);
        m.z = fmaxf(m.z, al.z); m.w = fmaxf(m.w, al.w);
        if (i < 64) { exb[w][i] = al; srcb[w][i] = s; }
    }
    #pragma unroll
    for (int o = 16; o; o >>= 1) {
        m.x = fmaxf(m.x, __shfl_xor_sync(0xffffffffu, m.x, o));
        m.y = fmaxf(m.y, __shfl_xor_sync(0xffffffffu, m.y, o));
        m.z = fmaxf(m.z, __shfl_xor_sync(0xffffffffu, m.z, o));
        m.w = fmaxf(m.w, __shfl_xor_sync(0xffffffffu, m.w, o));
    }

    float4 den = make_float4(0.f, 0.f, 0.f, 0.f);
    for (int i = lane; i < deg; i += 32) {
        float4 al;
        if (i < 64) al = exb[w][i];
        else {
            int s = g_csr_src[off + i];
            float4 ae = *(const float4*)&g_csr_ae[(size_t)(off + i) * 8 + aeoff];
            float4 as = *(const float4*)&g_asd[s * 8];
            al.x = lrelu(as.x + ad.x + ae.x); al.y = lrelu(as.y + ad.y + ae.y);
            al.z = lrelu(as.z + ad.z + ae.z); al.w = lrelu(as.w + ad.w + ae.w);
        }
        float4 ex;
        ex.x = __expf(al.x - m.x); ex.y = __expf(al.y - m.y);
        ex.z = __expf(al.z - m.z); ex.w = __expf(al.w - m.w);
        den.x += ex.x; den.y += ex.y; den.z += ex.z; den.w += ex.w;
        if (i < 64) exb[w][i] = ex;
    }
    #pragma unroll
    for (int o = 16; o; o >>= 1) {
        den.x += __shfl_xor_sync(0xffffffffu, den.x, o);
        den.y += __shfl_xor_sync(0xffffffffu, den.y, o);
        den.z += __shfl_xor_sync(0xffffffffu, den.z, o);
        den.w += __shfl_xor_sync(0xffffffffu, den.w, o);
    }
    __syncwarp();

    int hl = lane >> 3;
    float dh = sel4(den, hl);
    float mh = sel4(m, hl);
    float inv = 1.f / (dh + 1e-16f);
    float4 acc = make_float4(0.f, 0.f, 0.f, 0.f);
    #pragma unroll 4
    for (int i = 0; i < deg; i++) {
        float exh; int s;
        if (i < 64) {
            float4 e4 = exb[w][i];
            exh = sel4(e4, hl);
            s = srcb[w][i];
        } else {
            s = g_csr_src[off + i];
            float4 ae = *(const float4*)&g_csr_ae[(size_t)(off + i) * 8 + aeoff];
            float4 as = *(const float4*)&g_asd[s * 8];
            float4 al;
            al.x = lrelu(as.x + ad.x + ae.x); al.y = lrelu(as.y + ad.y + ae.y);
            al.z = lrelu(as.z + ad.z + ae.z); al.w = lrelu(as.w + ad.w + ae.w);
            exh = __expf(sel4(al, hl) - mh);
        }
        const float4 xv = *(const float4*)&x[(size_t)s * HC + lane * 4];
        acc.x = fmaf(exh, xv.x, acc.x);
        acc.y = fmaf(exh, xv.y, acc.y);
        acc.z = fmaf(exh, xv.z, acc.z);
        acc.w = fmaf(exh, xv.w, acc.w);
    }
    float4 b4 = *(const float4*)&bias[lane * 4];
    float4 r;
    r.x = fmaf(acc.x, inv, b4.x);
    r.y = fmaf(acc.y, inv, b4.y);
    r.z = fmaf(acc.z, inv, b4.z);
    r.w = fmaf(acc.w, inv, b4.w);
    r.x = r.x > 0.f ? r.x : expm1f(r.x);
    r.y = r.y > 0.f ? r.y : expm1f(r.y);
    r.z = r.z > 0.f ? r.z : expm1f(r.z);
    r.w = r.w > 0.f ? r.w : expm1f(r.w);
    *(float4*)&hout[(size_t)(n - outbase) * HC + lane * 4] = r;
}

// ---------------- mlp2 ----------------
__global__ void mlp2_kernel(const float* __restrict__ hid, const float* __restrict__ Wm2,
                            const float* __restrict__ bm2, float* __restrict__ out) {
    __shared__ float sW[FFH * ODIM];
    __shared__ float sb[ODIM];
    int t = threadIdx.x;
    if (t < FFH * ODIM) sW[t] = Wm2[t];
    if (t < ODIM) sb[t] = bm2[t];
    __syncthreads();
    int n = blockIdx.x * 256 + t;
    if (n >= NWAT) return;
    float a0 = sb[0], a1 = sb[1];
    #pragma unroll 4
    for (int k = 0; k < FFH; k++) {
        float v = hid[(size_t)n * FFH + k];
        a0 = fmaf(v, sW[2 * k], a0);
        a1 = fmaf(v, sW[2 * k + 1], a1);
    }
    out[n * 2] = a0;
    out[n * 2 + 1] = a1;
}

// ---------------- launch ----------------
extern "C" void kernel_launch(void* const* d_in, const int* in_sizes, int n_in,
                              void* d_out, int out_size) {
    static float *p_x = nullptr, *p_h1 = nullptr, *p_h2 = nullptr;
    if (!p_x) {
        cudaGetSymbolAddress((void**)&p_x,  g_x);
        cudaGetSymbolAddress((void**)&p_h1, g_h1);
        cudaGetSymbolAddress((void**)&p_h2, g_h2);
    }

    const float* ppos  = (const float*)d_in[0];
    const float* wpos  = (const float*)d_in[1];
    const float* pf    = (const float*)d_in[2];
    const int*   ei    = (const int*)d_in[3];
    const float* gamma = (const float*)d_in[4];
    const float* Wf    = (const float*)d_in[5];
    const float* bf    = (const float*)d_in[6];
    const float* We    = (const float*)d_in[7];
    const float* be    = (const float*)d_in[8];
    const float* W1    = (const float*)d_in[9];
    const float* atts1 = (const float*)d_in[10];
    const float* attd1 = (const float*)d_in[11];
    const float* Wedge1= (const float*)d_in[12];
    const float* atte1 = (const float*)d_in[13];
    const float* b1    = (const float*)d_in[14];
    const float* W2    = (const float*)d_in[15];
    const float* atts2 = (const float*)d_in[16];
    const float* attd2 = (const float*)d_in[17];
    const float* Wedge2= (const float*)d_in[18];
    const float* atte2 = (const float*)d_in[19];
    const float* b2    = (const float*)d_in[20];
    const float* Wm1   = (const float*)d_in[21];
    const float* bm1   = (const float*)d_in[22];
    const float* Wm2   = (const float*)d_in[23];
    const float* bm2   = (const float*)d_in[24];
    float* out = (float*)d_out;

    const int EB = (EE + 255) / 256;
    const int NB = (NN + 255) / 256;
    const int SB = (NN + 1023) / 1024;

    fold_kernel<<<1, 256>>>(We, be, Wedge1, atte1, Wedge2, atte2,
                            W1, atts1, attd1, W2, atts2, attd2, Wf, bf);
    zero_kernel<<<NB, 256>>>();
    count_kernel<<<EB, 256>>>(ei);
    scan1_kernel<<<SB, 1024>>>();
    scan2_kernel<<<1, 1>>>(SB);
    scan3_kernel<<<NB, 256>>>();
    edge_scatter<<<EB, 256>>>(ei, ppos, wpos, gamma);

    // layer 1: fused h0+gemm1+asd1
    node1_kernel<<<NB, 256>>>(pf);
    agg_kernel<<<(NN + 7) / 8, 256>>>(p_x, b1, p_h1, 0, NN, 0, 0);

    // layer 2 (aggregate only water dst nodes)
    gemm_nc128<128, false, false><<<(NN + 127) / 128, 256>>>(p_h1, W2, nullptr, p_x, NN);
    asd_kernel<128><<<(NN + 31) / 32, 256>>>(p_h1, FOLD_ASD2, NN);
    agg_kernel<<<(NWAT + 7) / 8, 256>>>(p_x, b2, p_h2, NPRO, NWAT, 4, NPRO);

    // MLP on water nodes only
    gemm_nc128<128, true, true><<<(NWAT + 127) / 128, 256>>>(p_h2, Wm1, bm1, p_x, NWAT);
    mlp2_kernel<<<(NWAT + 255) / 256, 256>>>(p_x, Wm2, bm2, out);
}

// round 13
// speedup vs baseline: 1.4122x; 1.3008x over previous
#include <cuda_runtime.h>
#include <cuda_bf16.h>
#include <cstdint>
#include <math.h>

// ---------------- problem constants ----------------
#define NPRO 60000
#define NWAT 40000
#define NN   100000
#define EE   1000000
#define INDIM 21
#define HIDC  32
#define HEADS 4
#define HC    128
#define EK    32
#define EDIM  32
#define FFH   128
#define ODIM  2
#define RADMAX 5.0f

#define FOLD_ME   0      // 32*8
#define FOLD_AEC  256    // 8
#define FOLD_ASD1 264    // 32*8 (intermediate for W1C)
#define FOLD_ASD2 520    // 128*8
#define FOLD_W1C  1544   // 21*136
#define FOLD_C1   4400   // 136

// ---------------- static device scratch ----------------
__device__ int   g_csr_src[EE];
__device__ float g_csr_ae[EE * 8];
__device__ int   g_rowptr[NN + 1];
__device__ int   g_cnt[NN];
__device__ int   g_cur[NN];
__device__ int   g_bsum[128];
__device__ float g_x[(size_t)NN * HC];
__device__ float g_h1[(size_t)NN * HC];
__device__ float g_h2[(size_t)NWAT * HC];
__device__ float g_asd[NN * 8];
__device__ float g_fold[8192];

__device__ __forceinline__ float lrelu(float x) { return fmaxf(x, 0.2f * x); }

// ---------------- fold kernel ----------------
__global__ void fold_kernel(const float* __restrict__ We,  const float* __restrict__ be,
                            const float* __restrict__ Wedge1, const float* __restrict__ atte1,
                            const float* __restrict__ Wedge2, const float* __restrict__ atte2,
                            const float* __restrict__ W1, const float* __restrict__ atts1, const float* __restrict__ attd1,
                            const float* __restrict__ W2, const float* __restrict__ atts2, const float* __restrict__ attd2,
                            const float* __restrict__ Wf, const float* __restrict__ bf) {
    __shared__ float Ve[2][EDIM][HEADS];
    int t = threadIdx.x;
    if (t < 256) {
        int l = t >> 7, r = t & 127, d = r >> 2, h = r & 3;
        const float* Wg = l ? Wedge2 : Wedge1;
        const float* ae = l ? atte2 : atte1;
        float s = 0.f;
        #pragma unroll
        for (int c = 0; c < 32; c++) s = fmaf(Wg[d * HC + h * 32 + c], ae[h * 32 + c], s);
        Ve[l][d][h] = s;
    }
    __syncthreads();
    if (t < 256) {
        int k = t >> 3, j = t & 7, l = j >> 2, h = j & 3;
        float s = 0.f;
        #pragma unroll
        for (int d = 0; d < 32; d++) s = fmaf(We[k * 32 + d], Ve[l][d][h], s);
        g_fold[FOLD_ME + k * 8 + j] = s;
    }
    if (t < 8) {
        int l = t >> 2, h = t & 3;
        float s = 0.f;
        for (int d = 0; d < 32; d++) s = fmaf(be[d], Ve[l][d][h], s);
        g_fold[FOLD_AEC + t] = s;
    }
    if (t < 256) {
        int d = t >> 3, j = t & 7, h = j & 3;
        const float* att = (j < 4) ? atts1 : attd1;
        float s = 0.f;
        #pragma unroll
        for (int c = 0; c < 32; c++) s = fmaf(W1[d * HC + h * 32 + c], att[h * 32 + c], s);
        g_fold[FOLD_ASD1 + d * 8 + j] = s;
    }
    for (int i = t; i < 1024; i += 256) {
        int d = i >> 3, j = i & 7, h = j & 3;
        const float* att = (j < 4) ? atts2 : attd2;
        float s = 0.f;
        #pragma unroll
        for (int c = 0; c < 32; c++) s = fmaf(W2[d * HC + h * 32 + c], att[h * 32 + c], s);
        g_fold[FOLD_ASD2 + i] = s;
    }
    __syncthreads();

    for (int i = t; i < INDIM * 136; i += 256) {
        int d = i / 136, c = i % 136;
        float s = 0.f;
        if (c < 128) {
            #pragma unroll
            for (int k = 0; k < 32; k++) s = fmaf(Wf[d * 32 + k], W1[k * 128 + c], s);
        } else {
            int j = c - 128;
            #pragma unroll
            for (int k = 0; k < 32; k++) s = fmaf(Wf[d * 32 + k], g_fold[FOLD_ASD1 + k * 8 + j], s);
        }
        g_fold[FOLD_W1C + i] = s;
    }
    for (int i = t; i < 136; i += 256) {
        float s = 0.f;
        if (i < 128) {
            #pragma unroll
            for (int k = 0; k < 32; k++) s = fmaf(bf[k], W1[k * 128 + i], s);
        } else {
            int j = i - 128;
            #pragma unroll
            for (int k = 0; k < 32; k++) s = fmaf(bf[k], g_fold[FOLD_ASD1 + k * 8 + j], s);
        }
        g_fold[FOLD_C1 + i] = s;
    }
}

__global__ void zero_kernel() {
    int i = blockIdx.x * 256 + threadIdx.x;
    if (i < NN) { g_cnt[i] = 0; g_cur[i] = 0; }
}

__global__ void count_kernel(const int* __restrict__ ei) {
    int e = blockIdx.x * 256 + threadIdx.x;
    if (e >= EE) return;
    int d = ei[EE + e];
    if ((unsigned)d >= NN) d = 0;
    atomicAdd(&g_cnt[d], 1);
}

__global__ void scan1_kernel() {
    __shared__ int sm[1024];
    int tid = threadIdx.x;
    int i = blockIdx.x * 1024 + tid;
    int v = (i < NN) ? g_cnt[i] : 0;
    sm[tid] = v;
    __syncthreads();
    for (int off = 1; off < 1024; off <<= 1) {
        int t = (tid >= off) ? sm[tid - off] : 0;
        __syncthreads();
        sm[tid] += t;
        __syncthreads();
    }
    if (i < NN) g_rowptr[i] = sm[tid] - v;
    if (tid == 1023) g_bsum[blockIdx.x] = sm[1023];
}
__global__ void scan2_kernel(int nb) {
    int run = 0;
    for (int b = 0; b < nb; b++) { int v = g_bsum[b]; g_bsum[b] = run; run += v; }
    g_rowptr[NN] = run;
}
__global__ void scan3_kernel() {
    int i = blockIdx.x * 256 + threadIdx.x;
    if (i < NN) g_rowptr[i] += g_bsum[i >> 10];
}

__global__ void edge_scatter(const int* __restrict__ ei,
                             const float* __restrict__ ppos, const float* __restrict__ wpos,
                             const float* __restrict__ gamma) {
    __shared__ float sMe[256];
    __shared__ float sAec[8];
    int t = threadIdx.x;
    if (t < 256) sMe[t] = g_fold[FOLD_ME + t];
    if (t < 8)   sAec[t] = g_fold[FOLD_AEC + t];
    __syncthreads();
    int e = blockIdx.x * 256 + t;
    if (e >= EE) return;
    int s = ei[e];
    int d = ei[EE + e];
    if ((unsigned)s >= NN) s = 0;
    if ((unsigned)d >= NN) d = 0;
    const float* ps = (s < NPRO) ? (ppos + 3 * s) : (wpos + 3 * (s - NPRO));
    const float* pd = (d < NPRO) ? (ppos + 3 * d) : (wpos + 3 * (d - NPRO));
    float dx = pd[0] - ps[0], dy = pd[1] - ps[1], dz = pd[2] - ps[2];
    float dis = sqrtf(dx * dx + dy * dy + dz * dz);
    float g = gamma[0];
    float acc[8];
    #pragma unroll
    for (int j = 0; j < 8; j++) acc[j] = sAec[j];
    #pragma unroll
    for (int k = 0; k < 32; k++) {
        float tt = dis - (float)k * (RADMAX / 31.0f);
        float r = __expf(-g * tt * tt);
        #pragma unroll
        for (int j = 0; j < 8; j++) acc[j] = fmaf(r, sMe[k * 8 + j], acc[j]);
    }
    int p = atomicAdd(&g_cur[d], 1);
    int idx = g_rowptr[d] + p;
    g_csr_src[idx] = s;
    float4* dp = (float4*)&g_csr_ae[(size_t)idx * 8];
    dp[0] = make_float4(acc[0], acc[1], acc[2], acc[3]);
    dp[1] = make_float4(acc[4], acc[5], acc[6], acc[7]);
}

// ---------------- fused node prep for layer 1 ----------------
__global__ __launch_bounds__(256) void node1_kernel(const float* __restrict__ pf) {
    __shared__ float sW[INDIM * 136];
    __shared__ float sC[136];
    __shared__ float sWat[136];
    int t = threadIdx.x;
    for (int i = t; i < INDIM * 136; i += 256) sW[i] = g_fold[FOLD_W1C + i];
    for (int i = t; i < 136; i += 256) {
        float c = g_fold[FOLD_C1 + i];
        sC[i] = c;
        sWat[i] = c + g_fold[FOLD_W1C + (INDIM - 1) * 136 + i];
    }
    __syncthreads();
    int n = blockIdx.x * 256 + t;
    if (n >= NN) return;
    if (n < NPRO) {
        float f[INDIM];
        #pragma unroll
        for (int d = 0; d < INDIM; d++) f[d] = pf[(size_t)n * INDIM + d];
        #pragma unroll 4
        for (int q = 0; q < 32; q++) {
            float4 a = *(const float4*)&sC[q * 4];
            #pragma unroll
            for (int d = 0; d < INDIM; d++) {
                float4 w = *(const float4*)&sW[d * 136 + q * 4];
                a.x = fmaf(f[d], w.x, a.x);
                a.y = fmaf(f[d], w.y, a.y);
                a.z = fmaf(f[d], w.z, a.z);
                a.w = fmaf(f[d], w.w, a.w);
            }
            *(float4*)&g_x[(size_t)n * HC + q * 4] = a;
        }
        #pragma unroll
        for (int q = 0; q < 2; q++) {
            float4 a = *(const float4*)&sC[128 + q * 4];
            #pragma unroll
            for (int d = 0; d < INDIM; d++) {
                float4 w = *(const float4*)&sW[d * 136 + 128 + q * 4];
                a.x = fmaf(f[d], w.x, a.x);
                a.y = fmaf(f[d], w.y, a.y);
                a.z = fmaf(f[d], w.z, a.z);
                a.w = fmaf(f[d], w.w, a.w);
            }
            *(float4*)&g_asd[n * 8 + q * 4] = a;
        }
    } else {
        #pragma unroll 4
        for (int q = 0; q < 32; q++)
            *(float4*)&g_x[(size_t)n * HC + q * 4] = *(const float4*)&sWat[q * 4];
        #pragma unroll
        for (int q = 0; q < 2; q++)
            *(float4*)&g_asd[n * 8 + q * 4] = *(const float4*)&sWat[128 + q * 4];
    }
}

// ---------------- tensor-core GEMM: C[M,128] = act(A[M,128]@W[128,128] (+bias)) ----------------
__device__ __forceinline__ void mma_bf16(float* d, const uint32_t* a, uint32_t b0, uint32_t b1) {
    asm volatile(
        "mma.sync.aligned.m16n8k16.row.col.f32.bf16.bf16.f32 "
        "{%0,%1,%2,%3}, {%4,%5,%6,%7}, {%8,%9}, {%0,%1,%2,%3};\n"
        : "+f"(d[0]), "+f"(d[1]), "+f"(d[2]), "+f"(d[3])
        : "r"(a[0]), "r"(a[1]), "r"(a[2]), "r"(a[3]), "r"(b0), "r"(b1));
}
__device__ __forceinline__ void split_pack(float v0, float v1, uint32_t& hi, uint32_t& lo) {
    __nv_bfloat16 h0 = __float2bfloat16_rn(v0), h1 = __float2bfloat16_rn(v1);
    float l0 = v0 - __bfloat162float(h0), l1 = v1 - __bfloat162float(h1);
    __nv_bfloat16 e0 = __float2bfloat16_rn(l0), e1 = __float2bfloat16_rn(l1);
    hi = (uint32_t)__bfloat16_as_ushort(h0) | ((uint32_t)__bfloat16_as_ushort(h1) << 16);
    lo = (uint32_t)__bfloat16_as_ushort(e0) | ((uint32_t)__bfloat16_as_ushort(e1) << 16);
}

template<bool RELU, bool BIAS>
__global__ __launch_bounds__(256) void gemm_tc128(const float* __restrict__ A,
                                                  const float* __restrict__ W,
                                                  const float* __restrict__ bias,
                                                  float* __restrict__ C, int M) {
    __shared__ uint32_t sAh[128][17], sAl[128][17];   // [m][kk] k-pairs (k=2kk, 2kk+1)
    __shared__ uint32_t sBh[128][17], sBl[128][17];   // [n][kk]
    int tid = threadIdx.x;
    int lane = tid & 31, wid = tid >> 5;
    int wm = wid >> 1, wn = wid & 1;            // warp tile: 32(M) x 64(N)
    int qr = lane >> 2, qc = lane & 3;
    int row0 = blockIdx.x * 128;

    float d[2][8][4];
    #pragma unroll
    for (int mt = 0; mt < 2; mt++)
        #pragma unroll
        for (int nt = 0; nt < 8; nt++)
            #pragma unroll
            for (int r = 0; r < 4; r++) d[mt][nt][r] = 0.f;

    for (int kc = 0; kc < 128; kc += 32) {
        // A chunk: 128 rows x 16 k-pairs (float2 along k, coalesced)
        for (int idx = tid; idx < 128 * 16; idx += 256) {
            int m = idx >> 4, kk = idx & 15;
            int gr = row0 + m;
            float2 v = make_float2(0.f, 0.f);
            if (gr < M) v = *(const float2*)&A[(size_t)gr * 128 + kc + 2 * kk];
            split_pack(v.x, v.y, sAh[m][kk], sAl[m][kk]);
        }
        // B chunk: transpose W rows into [n][kk] pairs (coalesced across n)
        for (int idx = tid; idx < 128 * 16; idx += 256) {
            int n = idx & 127, kk = idx >> 7;
            int k = kc + 2 * kk;
            float w0 = W[(size_t)k * 128 + n];
            float w1 = W[(size_t)(k + 1) * 128 + n];
            split_pack(w0, w1, sBh[n][kk], sBl[n][kk]);
        }
        __syncthreads();

        #pragma unroll
        for (int ks = 0; ks < 2; ks++) {
            int kk0 = ks * 8;
            uint32_t ah[2][4], al[2][4];
            #pragma unroll
            for (int mt = 0; mt < 2; mt++) {
                int mb = wm * 32 + mt * 16;
                ah[mt][0] = sAh[mb + qr][kk0 + qc];
                ah[mt][1] = sAh[mb + qr + 8][kk0 + qc];
                ah[mt][2] = sAh[mb + qr][kk0 + 4 + qc];
                ah[mt][3] = sAh[mb + qr + 8][kk0 + 4 + qc];
                al[mt][0] = sAl[mb + qr][kk0 + qc];
                al[mt][1] = sAl[mb + qr + 8][kk0 + qc];
                al[mt][2] = sAl[mb + qr][kk0 + 4 + qc];
                al[mt][3] = sAl[mb + qr + 8][kk0 + 4 + qc];
            }
            #pragma unroll
            for (int nt = 0; nt < 8; nt++) {
                int nb = wn * 64 + nt * 8;
                uint32_t bh0 = sBh[nb + qr][kk0 + qc], bh1 = sBh[nb + qr][kk0 + 4 + qc];
                uint32_t bl0 = sBl[nb + qr][kk0 + qc], bl1 = sBl[nb + qr][kk0 + 4 + qc];
                #pragma unroll
                for (int mt = 0; mt < 2; mt++) {
                    mma_bf16(d[mt][nt], ah[mt], bh0, bh1);
                    mma_bf16(d[mt][nt], ah[mt], bl0, bl1);
                    mma_bf16(d[mt][nt], al[mt], bh0, bh1);
                }
            }
        }
        __syncthreads();
    }

    // epilogue
    #pragma unroll
    for (int mt = 0; mt < 2; mt++) {
        #pragma unroll
        for (int nt = 0; nt < 8; nt++) {
            int c0 = wn * 64 + nt * 8 + 2 * qc;
            float bb0 = BIAS ? bias[c0] : 0.f;
            float bb1 = BIAS ? bias[c0 + 1] : 0.f;
            int r0 = row0 + wm * 32 + mt * 16 + qr;
            int r1 = r0 + 8;
            if (r0 < M) {
                float v0 = d[mt][nt][0] + bb0, v1 = d[mt][nt][1] + bb1;
                if (RELU) { v0 = fmaxf(v0, 0.f); v1 = fmaxf(v1, 0.f); }
                C[(size_t)r0 * 128 + c0] = v0;
                C[(size_t)r0 * 128 + c0 + 1] = v1;
            }
            if (r1 < M) {
                float v2 = d[mt][nt][2] + bb0, v3 = d[mt][nt][3] + bb1;
                if (RELU) { v2 = fmaxf(v2, 0.f); v3 = fmaxf(v3, 0.f); }
                C[(size_t)r1 * 128 + c0] = v2;
                C[(size_t)r1 * 128 + c0 + 1] = v3;
            }
        }
    }
}

// ---------------- asd (layer 2) ----------------
template<int K>
__global__ void asd_kernel(const float* __restrict__ h, int foldoff, int M) {
    __shared__ float sf[K * 8];
    __shared__ float sh[32][K];
    int t = threadIdx.x;
    for (int i = t; i < K * 8; i += 256) sf[i] = g_fold[foldoff + i];
    int n0 = blockIdx.x * 32;
    for (int i = t; i < 32 * K; i += 256) {
        int r = i / K, k = i % K;
        int gn = n0 + r;
        sh[r][k] = (gn < M) ? h[(size_t)gn * K + k] : 0.f;
    }
    __syncthreads();
    int r = t >> 3, j = t & 7;
    int gn = n0 + r;
    if (gn < M) {
        float a = 0.f;
        #pragma unroll
        for (int k = 0; k < K; k++) a = fmaf(sh[r][k], sf[k * 8 + j], a);
        g_asd[gn * 8 + j] = a;
    }
}

// ---------------- agg ----------------
__device__ __forceinline__ float sel4(float4 v, int h) {
    return (h & 2) ? ((h & 1) ? v.w : v.z) : ((h & 1) ? v.y : v.x);
}

__global__ __launch_bounds__(256) void agg_kernel(const float* __restrict__ x,
                                                  const float* __restrict__ bias,
                                                  float* __restrict__ hout,
                                                  int nbase, int ncount, int aeoff, int outbase) {
    __shared__ float4 exb[8][64];
    __shared__ int    srcb[8][64];
    int lane = threadIdx.x & 31, w = threadIdx.x >> 5;
    int n = nbase + blockIdx.x * 8 + w;
    if (n >= nbase + ncount) return;
    int off = g_rowptr[n];
    int deg = g_rowptr[n + 1] - off;
    const float4 ad = *(const float4*)&g_asd[n * 8 + 4];

    float4 m = make_float4(-1e30f, -1e30f, -1e30f, -1e30f);
    for (int i = lane; i < deg; i += 32) {
        int s = g_csr_src[off + i];
        float4 ae = *(const float4*)&g_csr_ae[(size_t)(off + i) * 8 + aeoff];
        float4 as = *(const float4*)&g_asd[s * 8];
        float4 al;
        al.x = lrelu(as.x + ad.x + ae.x);
        al.y = lrelu(as.y + ad.y + ae.y);
        al.z = lrelu(as.z + ad.z + ae.z);
        al.w = lrelu(as.w + ad.w + ae.w);
        m.x = fmaxf(m.x, al.x); m.y = fmaxf(m.y, al.y);
        m.z = fmaxf(m.z, al.z); m.w = fmaxf(m.w, al.w);
        if (i < 64) { exb[w][i] = al; srcb[w][i] = s; }
    }
    #pragma unroll
    for (int o = 16; o; o >>= 1) {
        m.x = fmaxf(m.x, __shfl_xor_sync(0xffffffffu, m.x, o));
        m.y = fmaxf(m.y, __shfl_xor_sync(0xffffffffu, m.y, o));
        m.z = fmaxf(m.z, __shfl_xor_sync(0xffffffffu, m.z, o));
        m.w = fmaxf(m.w, __shfl_xor_sync(0xffffffffu, m.w, o));
    }

    float4 den = make_float4(0.f, 0.f, 0.f, 0.f);
    for (int i = lane; i < deg; i += 32) {
        float4 al;
        if (i < 64) al = exb[w][i];
        else {
            int s = g_csr_src[off + i];
            float4 ae = *(const float4*)&g_csr_ae[(size_t)(off + i) * 8 + aeoff];
            float4 as = *(const float4*)&g_asd[s * 8];
            al.x = lrelu(as.x + ad.x + ae.x); al.y = lrelu(as.y + ad.y + ae.y);
            al.z = lrelu(as.z + ad.z + ae.z); al.w = lrelu(as.w + ad.w + ae.w);
        }
        float4 ex;
        ex.x = __expf(al.x - m.x); ex.y = __expf(al.y - m.y);
        ex.z = __expf(al.z - m.z); ex.w = __expf(al.w - m.w);
        den.x += ex.x; den.y += ex.y; den.z += ex.z; den.w += ex.w;
        if (i < 64) exb[w][i] = ex;
    }
    #pragma unroll
    for (int o = 16; o; o >>= 1) {
        den.x += __shfl_xor_sync(0xffffffffu, den.x, o);
        den.y += __shfl_xor_sync(0xffffffffu, den.y, o);
        den.z += __shfl_xor_sync(0xffffffffu, den.z, o);
        den.w += __shfl_xor_sync(0xffffffffu, den.w, o);
    }
    __syncwarp();

    int hl = lane >> 3;
    float dh = sel4(den, hl);
    float mh = sel4(m, hl);
    float inv = 1.f / (dh + 1e-16f);
    float4 acc = make_float4(0.f, 0.f, 0.f, 0.f);
    #pragma unroll 4
    for (int i = 0; i < deg; i++) {
        float exh; int s;
        if (i < 64) {
            float4 e4 = exb[w][i];
            exh = sel4(e4, hl);
            s = srcb[w][i];
        } else {
            s = g_csr_src[off + i];
            float4 ae = *(const float4*)&g_csr_ae[(size_t)(off + i) * 8 + aeoff];
            float4 as = *(const float4*)&g_asd[s * 8];
            float4 al;
            al.x = lrelu(as.x + ad.x + ae.x); al.y = lrelu(as.y + ad.y + ae.y);
            al.z = lrelu(as.z + ad.z + ae.z); al.w = lrelu(as.w + ad.w + ae.w);
            exh = __expf(sel4(al, hl) - mh);
        }
        const float4 xv = *(const float4*)&x[(size_t)s * HC + lane * 4];
        acc.x = fmaf(exh, xv.x, acc.x);
        acc.y = fmaf(exh, xv.y, acc.y);
        acc.z = fmaf(exh, xv.z, acc.z);
        acc.w = fmaf(exh, xv.w, acc.w);
    }
    float4 b4 = *(const float4*)&bias[lane * 4];
    float4 r;
    r.x = fmaf(acc.x, inv, b4.x);
    r.y = fmaf(acc.y, inv, b4.y);
    r.z = fmaf(acc.z, inv, b4.z);
    r.w = fmaf(acc.w, inv, b4.w);
    r.x = r.x > 0.f ? r.x : expm1f(r.x);
    r.y = r.y > 0.f ? r.y : expm1f(r.y);
    r.z = r.z > 0.f ? r.z : expm1f(r.z);
    r.w = r.w > 0.f ? r.w : expm1f(r.w);
    *(float4*)&hout[(size_t)(n - outbase) * HC + lane * 4] = r;
}

// ---------------- mlp2 ----------------
__global__ void mlp2_kernel(const float* __restrict__ hid, const float* __restrict__ Wm2,
                            const float* __restrict__ bm2, float* __restrict__ out) {
    __shared__ float sW[FFH * ODIM];
    __shared__ float sb[ODIM];
    int t = threadIdx.x;
    if (t < FFH * ODIM) sW[t] = Wm2[t];
    if (t < ODIM) sb[t] = bm2[t];
    __syncthreads();
    int n = blockIdx.x * 256 + t;
    if (n >= NWAT) return;
    float a0 = sb[0], a1 = sb[1];
    #pragma unroll 4
    for (int k = 0; k < FFH; k++) {
        float v = hid[(size_t)n * FFH + k];
        a0 = fmaf(v, sW[2 * k], a0);
        a1 = fmaf(v, sW[2 * k + 1], a1);
    }
    out[n * 2] = a0;
    out[n * 2 + 1] = a1;
}

// ---------------- launch ----------------
extern "C" void kernel_launch(void* const* d_in, const int* in_sizes, int n_in,
                              void* d_out, int out_size) {
    static float *p_x = nullptr, *p_h1 = nullptr, *p_h2 = nullptr;
    if (!p_x) {
        cudaGetSymbolAddress((void**)&p_x,  g_x);
        cudaGetSymbolAddress((void**)&p_h1, g_h1);
        cudaGetSymbolAddress((void**)&p_h2, g_h2);
    }

    const float* ppos  = (const float*)d_in[0];
    const float* wpos  = (const float*)d_in[1];
    const float* pf    = (const float*)d_in[2];
    const int*   ei    = (const int*)d_in[3];
    const float* gamma = (const float*)d_in[4];
    const float* Wf    = (const float*)d_in[5];
    const float* bf    = (const float*)d_in[6];
    const float* We    = (const float*)d_in[7];
    const float* be    = (const float*)d_in[8];
    const float* W1    = (const float*)d_in[9];
    const float* atts1 = (const float*)d_in[10];
    const float* attd1 = (const float*)d_in[11];
    const float* Wedge1= (const float*)d_in[12];
    const float* atte1 = (const float*)d_in[13];
    const float* b1    = (const float*)d_in[14];
    const float* W2    = (const float*)d_in[15];
    const float* atts2 = (const float*)d_in[16];
    const float* attd2 = (const float*)d_in[17];
    const float* Wedge2= (const float*)d_in[18];
    const float* atte2 = (const float*)d_in[19];
    const float* b2    = (const float*)d_in[20];
    const float* Wm1   = (const float*)d_in[21];
    const float* bm1   = (const float*)d_in[22];
    const float* Wm2   = (const float*)d_in[23];
    const float* bm2   = (const float*)d_in[24];
    float* out = (float*)d_out;

    const int EB = (EE + 255) / 256;
    const int NB = (NN + 255) / 256;
    const int SB = (NN + 1023) / 1024;

    fold_kernel<<<1, 256>>>(We, be, Wedge1, atte1, Wedge2, atte2,
                            W1, atts1, attd1, W2, atts2, attd2, Wf, bf);
    zero_kernel<<<NB, 256>>>();
    count_kernel<<<EB, 256>>>(ei);
    scan1_kernel<<<SB, 1024>>>();
    scan2_kernel<<<1, 1>>>(SB);
    scan3_kernel<<<NB, 256>>>();
    edge_scatter<<<EB, 256>>>(ei, ppos, wpos, gamma);

    // layer 1: fused h0+gemm1+asd1
    node1_kernel<<<NB, 256>>>(pf);
    agg_kernel<<<(NN + 7) / 8, 256>>>(p_x, b1, p_h1, 0, NN, 0, 0);

    // layer 2 (tensor-core GEMM; aggregate only water dst nodes)
    gemm_tc128<false, false><<<(NN + 127) / 128, 256>>>(p_h1, W2, nullptr, p_x, NN);
    asd_kernel<128><<<(NN + 31) / 32, 256>>>(p_h1, FOLD_ASD2, NN);
    agg_kernel<<<(NWAT + 7) / 8, 256>>>(p_x, b2, p_h2, NPRO, NWAT, 4, NPRO);

    // MLP on water nodes only (tensor-core)
    gemm_tc128<true, true><<<(NWAT + 127) / 128, 256>>>(p_h2, Wm1, bm1, p_x, NWAT);
    mlp2_kernel<<<(NWAT + 255) / 256, 256>>>(p_x, Wm2, bm2, out);
}

// round 14
// speedup vs baseline: 1.5286x; 1.0824x over previous
#include <cuda_runtime.h>
#include <cuda_bf16.h>
#include <cstdint>
#include <math.h>

// ---------------- problem constants ----------------
#define NPRO 60000
#define NWAT 40000
#define NN   100000
#define EE   1000000
#define INDIM 21
#define HIDC  32
#define HEADS 4
#define HC    128
#define EK    32
#define EDIM  32
#define FFH   128
#define ODIM  2
#define RADMAX 5.0f

#define FOLD_ME   0      // 32*8
#define FOLD_AEC  256    // 8
#define FOLD_ASD1 264    // 32*8 (intermediate for W1C)
#define FOLD_ASD2 520    // 128*8
#define FOLD_W1C  1544   // 21*136
#define FOLD_C1   4400   // 136

// ---------------- static device scratch ----------------
__device__ int   g_csr_src[EE];
__device__ float g_csr_ae[EE * 8];
__device__ int   g_rowptr[NN + 1];
__device__ int   g_cnt[NN];
__device__ int   g_cur[NN];
__device__ int   g_bsum[128];
__device__ float g_x[(size_t)NN * HC];
__device__ float g_h1[(size_t)NN * HC];
__device__ float g_h2[(size_t)NWAT * HC];
__device__ float g_asd[NN * 8];
__device__ float g_fold[8192];

__device__ __forceinline__ float lrelu(float x) { return fmaxf(x, 0.2f * x); }

// ---------------- fold kernel ----------------
__global__ void fold_kernel(const float* __restrict__ We,  const float* __restrict__ be,
                            const float* __restrict__ Wedge1, const float* __restrict__ atte1,
                            const float* __restrict__ Wedge2, const float* __restrict__ atte2,
                            const float* __restrict__ W1, const float* __restrict__ atts1, const float* __restrict__ attd1,
                            const float* __restrict__ W2, const float* __restrict__ atts2, const float* __restrict__ attd2,
                            const float* __restrict__ Wf, const float* __restrict__ bf) {
    __shared__ float Ve[2][EDIM][HEADS];
    int t = threadIdx.x;
    if (t < 256) {
        int l = t >> 7, r = t & 127, d = r >> 2, h = r & 3;
        const float* Wg = l ? Wedge2 : Wedge1;
        const float* ae = l ? atte2 : atte1;
        float s = 0.f;
        #pragma unroll
        for (int c = 0; c < 32; c++) s = fmaf(Wg[d * HC + h * 32 + c], ae[h * 32 + c], s);
        Ve[l][d][h] = s;
    }
    __syncthreads();
    if (t < 256) {
        int k = t >> 3, j = t & 7, l = j >> 2, h = j & 3;
        float s = 0.f;
        #pragma unroll
        for (int d = 0; d < 32; d++) s = fmaf(We[k * 32 + d], Ve[l][d][h], s);
        g_fold[FOLD_ME + k * 8 + j] = s;
    }
    if (t < 8) {
        int l = t >> 2, h = t & 3;
        float s = 0.f;
        for (int d = 0; d < 32; d++) s = fmaf(be[d], Ve[l][d][h], s);
        g_fold[FOLD_AEC + t] = s;
    }
    if (t < 256) {
        int d = t >> 3, j = t & 7, h = j & 3;
        const float* att = (j < 4) ? atts1 : attd1;
        float s = 0.f;
        #pragma unroll
        for (int c = 0; c < 32; c++) s = fmaf(W1[d * HC + h * 32 + c], att[h * 32 + c], s);
        g_fold[FOLD_ASD1 + d * 8 + j] = s;
    }
    for (int i = t; i < 1024; i += 256) {
        int d = i >> 3, j = i & 7, h = j & 3;
        const float* att = (j < 4) ? atts2 : attd2;
        float s = 0.f;
        #pragma unroll
        for (int c = 0; c < 32; c++) s = fmaf(W2[d * HC + h * 32 + c], att[h * 32 + c], s);
        g_fold[FOLD_ASD2 + i] = s;
    }
    __syncthreads();

    for (int i = t; i < INDIM * 136; i += 256) {
        int d = i / 136, c = i % 136;
        float s = 0.f;
        if (c < 128) {
            #pragma unroll
            for (int k = 0; k < 32; k++) s = fmaf(Wf[d * 32 + k], W1[k * 128 + c], s);
        } else {
            int j = c - 128;
            #pragma unroll
            for (int k = 0; k < 32; k++) s = fmaf(Wf[d * 32 + k], g_fold[FOLD_ASD1 + k * 8 + j], s);
        }
        g_fold[FOLD_W1C + i] = s;
    }
    for (int i = t; i < 136; i += 256) {
        float s = 0.f;
        if (i < 128) {
            #pragma unroll
            for (int k = 0; k < 32; k++) s = fmaf(bf[k], W1[k * 128 + i], s);
        } else {
            int j = i - 128;
            #pragma unroll
            for (int k = 0; k < 32; k++) s = fmaf(bf[k], g_fold[FOLD_ASD1 + k * 8 + j], s);
        }
        g_fold[FOLD_C1 + i] = s;
    }
}

__global__ void zero_kernel() {
    int i = blockIdx.x * 256 + threadIdx.x;
    if (i < NN) { g_cnt[i] = 0; g_cur[i] = 0; }
}

__global__ void count_kernel(const int* __restrict__ ei) {
    int e = blockIdx.x * 256 + threadIdx.x;
    if (e >= EE) return;
    int d = ei[EE + e];
    if ((unsigned)d >= NN) d = 0;
    atomicAdd(&g_cnt[d], 1);
}

__global__ void scan1_kernel() {
    __shared__ int sm[1024];
    int tid = threadIdx.x;
    int i = blockIdx.x * 1024 + tid;
    int v = (i < NN) ? g_cnt[i] : 0;
    sm[tid] = v;
    __syncthreads();
    for (int off = 1; off < 1024; off <<= 1) {
        int t = (tid >= off) ? sm[tid - off] : 0;
        __syncthreads();
        sm[tid] += t;
        __syncthreads();
    }
    if (i < NN) g_rowptr[i] = sm[tid] - v;
    if (tid == 1023) g_bsum[blockIdx.x] = sm[1023];
}
__global__ void scan2_kernel(int nb) {
    int run = 0;
    for (int b = 0; b < nb; b++) { int v = g_bsum[b]; g_bsum[b] = run; run += v; }
    g_rowptr[NN] = run;
}
__global__ void scan3_kernel() {
    int i = blockIdx.x * 256 + threadIdx.x;
    if (i < NN) g_rowptr[i] += g_bsum[i >> 10];
}

__global__ void edge_scatter(const int* __restrict__ ei,
                             const float* __restrict__ ppos, const float* __restrict__ wpos,
                             const float* __restrict__ gamma) {
    __shared__ float sMe[256];
    __shared__ float sAec[8];
    int t = threadIdx.x;
    if (t < 256) sMe[t] = g_fold[FOLD_ME + t];
    if (t < 8)   sAec[t] = g_fold[FOLD_AEC + t];
    __syncthreads();
    int e = blockIdx.x * 256 + t;
    if (e >= EE) return;
    int s = ei[e];
    int d = ei[EE + e];
    if ((unsigned)s >= NN) s = 0;
    if ((unsigned)d >= NN) d = 0;
    const float* ps = (s < NPRO) ? (ppos + 3 * s) : (wpos + 3 * (s - NPRO));
    const float* pd = (d < NPRO) ? (ppos + 3 * d) : (wpos + 3 * (d - NPRO));
    float dx = pd[0] - ps[0], dy = pd[1] - ps[1], dz = pd[2] - ps[2];
    float dis = sqrtf(dx * dx + dy * dy + dz * dz);
    float g = gamma[0];
    float acc[8];
    #pragma unroll
    for (int j = 0; j < 8; j++) acc[j] = sAec[j];
    #pragma unroll
    for (int k = 0; k < 32; k++) {
        float tt = dis - (float)k * (RADMAX / 31.0f);
        float r = __expf(-g * tt * tt);
        #pragma unroll
        for (int j = 0; j < 8; j++) acc[j] = fmaf(r, sMe[k * 8 + j], acc[j]);
    }
    int p = atomicAdd(&g_cur[d], 1);
    int idx = g_rowptr[d] + p;
    g_csr_src[idx] = s;
    float4* dp = (float4*)&g_csr_ae[(size_t)idx * 8];
    dp[0] = make_float4(acc[0], acc[1], acc[2], acc[3]);
    dp[1] = make_float4(acc[4], acc[5], acc[6], acc[7]);
}

// ---------------- fused node prep for layer 1 ----------------
__global__ __launch_bounds__(256) void node1_kernel(const float* __restrict__ pf) {
    __shared__ float sW[INDIM * 136];
    __shared__ float sC[136];
    __shared__ float sWat[136];
    int t = threadIdx.x;
    for (int i = t; i < INDIM * 136; i += 256) sW[i] = g_fold[FOLD_W1C + i];
    for (int i = t; i < 136; i += 256) {
        float c = g_fold[FOLD_C1 + i];
        sC[i] = c;
        sWat[i] = c + g_fold[FOLD_W1C + (INDIM - 1) * 136 + i];
    }
    __syncthreads();
    int n = blockIdx.x * 256 + t;
    if (n >= NN) return;
    if (n < NPRO) {
        float f[INDIM];
        #pragma unroll
        for (int d = 0; d < INDIM; d++) f[d] = pf[(size_t)n * INDIM + d];
        #pragma unroll 4
        for (int q = 0; q < 32; q++) {
            float4 a = *(const float4*)&sC[q * 4];
            #pragma unroll
            for (int d = 0; d < INDIM; d++) {
                float4 w = *(const float4*)&sW[d * 136 + q * 4];
                a.x = fmaf(f[d], w.x, a.x);
                a.y = fmaf(f[d], w.y, a.y);
                a.z = fmaf(f[d], w.z, a.z);
                a.w = fmaf(f[d], w.w, a.w);
            }
            *(float4*)&g_x[(size_t)n * HC + q * 4] = a;
        }
        #pragma unroll
        for (int q = 0; q < 2; q++) {
            float4 a = *(const float4*)&sC[128 + q * 4];
            #pragma unroll
            for (int d = 0; d < INDIM; d++) {
                float4 w = *(const float4*)&sW[d * 136 + 128 + q * 4];
                a.x = fmaf(f[d], w.x, a.x);
                a.y = fmaf(f[d], w.y, a.y);
                a.z = fmaf(f[d], w.z, a.z);
                a.w = fmaf(f[d], w.w, a.w);
            }
            *(float4*)&g_asd[n * 8 + q * 4] = a;
        }
    } else {
        #pragma unroll 4
        for (int q = 0; q < 32; q++)
            *(float4*)&g_x[(size_t)n * HC + q * 4] = *(const float4*)&sWat[q * 4];
        #pragma unroll
        for (int q = 0; q < 2; q++)
            *(float4*)&g_asd[n * 8 + q * 4] = *(const float4*)&sWat[128 + q * 4];
    }
}

// ---------------- tensor-core GEMM ----------------
__device__ __forceinline__ void mma_bf16(float* d, const uint32_t* a, uint32_t b0, uint32_t b1) {
    asm volatile(
        "mma.sync.aligned.m16n8k16.row.col.f32.bf16.bf16.f32 "
        "{%0,%1,%2,%3}, {%4,%5,%6,%7}, {%8,%9}, {%0,%1,%2,%3};\n"
        : "+f"(d[0]), "+f"(d[1]), "+f"(d[2]), "+f"(d[3])
        : "r"(a[0]), "r"(a[1]), "r"(a[2]), "r"(a[3]), "r"(b0), "r"(b1));
}
__device__ __forceinline__ void split_pack(float v0, float v1, uint32_t& hi, uint32_t& lo) {
    __nv_bfloat16 h0 = __float2bfloat16_rn(v0), h1 = __float2bfloat16_rn(v1);
    float l0 = v0 - __bfloat162float(h0), l1 = v1 - __bfloat162float(h1);
    __nv_bfloat16 e0 = __float2bfloat16_rn(l0), e1 = __float2bfloat16_rn(l1);
    hi = (uint32_t)__bfloat16_as_ushort(h0) | ((uint32_t)__bfloat16_as_ushort(h1) << 16);
    lo = (uint32_t)__bfloat16_as_ushort(e0) | ((uint32_t)__bfloat16_as_ushort(e1) << 16);
}

template<bool RELU, bool BIAS>
__global__ __launch_bounds__(256) void gemm_tc128(const float* __restrict__ A,
                                                  const float* __restrict__ W,
                                                  const float* __restrict__ bias,
                                                  float* __restrict__ C, int M) {
    __shared__ uint32_t sAh[128][17], sAl[128][17];
    __shared__ uint32_t sBh[128][17], sBl[128][17];
    int tid = threadIdx.x;
    int lane = tid & 31, wid = tid >> 5;
    int wm = wid >> 1, wn = wid & 1;
    int qr = lane >> 2, qc = lane & 3;
    int row0 = blockIdx.x * 128;

    float d[2][8][4];
    #pragma unroll
    for (int mt = 0; mt < 2; mt++)
        #pragma unroll
        for (int nt = 0; nt < 8; nt++)
            #pragma unroll
            for (int r = 0; r < 4; r++) d[mt][nt][r] = 0.f;

    for (int kc = 0; kc < 128; kc += 32) {
        for (int idx = tid; idx < 128 * 16; idx += 256) {
            int m = idx >> 4, kk = idx & 15;
            int gr = row0 + m;
            float2 v = make_float2(0.f, 0.f);
            if (gr < M) v = *(const float2*)&A[(size_t)gr * 128 + kc + 2 * kk];
            split_pack(v.x, v.y, sAh[m][kk], sAl[m][kk]);
        }
        for (int idx = tid; idx < 128 * 16; idx += 256) {
            int n = idx & 127, kk = idx >> 7;
            int k = kc + 2 * kk;
            float w0 = W[(size_t)k * 128 + n];
            float w1 = W[(size_t)(k + 1) * 128 + n];
            split_pack(w0, w1, sBh[n][kk], sBl[n][kk]);
        }
        __syncthreads();

        #pragma unroll
        for (int ks = 0; ks < 2; ks++) {
            int kk0 = ks * 8;
            uint32_t ah[2][4], al[2][4];
            #pragma unroll
            for (int mt = 0; mt < 2; mt++) {
                int mb = wm * 32 + mt * 16;
                ah[mt][0] = sAh[mb + qr][kk0 + qc];
                ah[mt][1] = sAh[mb + qr + 8][kk0 + qc];
                ah[mt][2] = sAh[mb + qr][kk0 + 4 + qc];
                ah[mt][3] = sAh[mb + qr + 8][kk0 + 4 + qc];
                al[mt][0] = sAl[mb + qr][kk0 + qc];
                al[mt][1] = sAl[mb + qr + 8][kk0 + qc];
                al[mt][2] = sAl[mb + qr][kk0 + 4 + qc];
                al[mt][3] = sAl[mb + qr + 8][kk0 + 4 + qc];
            }
            #pragma unroll
            for (int nt = 0; nt < 8; nt++) {
                int nb = wn * 64 + nt * 8;
                uint32_t bh0 = sBh[nb + qr][kk0 + qc], bh1 = sBh[nb + qr][kk0 + 4 + qc];
                uint32_t bl0 = sBl[nb + qr][kk0 + qc], bl1 = sBl[nb + qr][kk0 + 4 + qc];
                #pragma unroll
                for (int mt = 0; mt < 2; mt++) {
                    mma_bf16(d[mt][nt], ah[mt], bh0, bh1);
                    mma_bf16(d[mt][nt], ah[mt], bl0, bl1);
                    mma_bf16(d[mt][nt], al[mt], bh0, bh1);
                }
            }
        }
        __syncthreads();
    }

    #pragma unroll
    for (int mt = 0; mt < 2; mt++) {
        #pragma unroll
        for (int nt = 0; nt < 8; nt++) {
            int c0 = wn * 64 + nt * 8 + 2 * qc;
            float bb0 = BIAS ? bias[c0] : 0.f;
            float bb1 = BIAS ? bias[c0 + 1] : 0.f;
            int r0 = row0 + wm * 32 + mt * 16 + qr;
            int r1 = r0 + 8;
            if (r0 < M) {
                float v0 = d[mt][nt][0] + bb0, v1 = d[mt][nt][1] + bb1;
                if (RELU) { v0 = fmaxf(v0, 0.f); v1 = fmaxf(v1, 0.f); }
                C[(size_t)r0 * 128 + c0] = v0;
                C[(size_t)r0 * 128 + c0 + 1] = v1;
            }
            if (r1 < M) {
                float v2 = d[mt][nt][2] + bb0, v3 = d[mt][nt][3] + bb1;
                if (RELU) { v2 = fmaxf(v2, 0.f); v3 = fmaxf(v3, 0.f); }
                C[(size_t)r1 * 128 + c0] = v2;
                C[(size_t)r1 * 128 + c0 + 1] = v3;
            }
        }
    }
}

// ---------------- asd (layer 2) ----------------
template<int K>
__global__ void asd_kernel(const float* __restrict__ h, int foldoff, int M) {
    __shared__ float sf[K * 8];
    __shared__ float sh[32][K];
    int t = threadIdx.x;
    for (int i = t; i < K * 8; i += 256) sf[i] = g_fold[foldoff + i];
    int n0 = blockIdx.x * 32;
    for (int i = t; i < 32 * K; i += 256) {
        int r = i / K, k = i % K;
        int gn = n0 + r;
        sh[r][k] = (gn < M) ? h[(size_t)gn * K + k] : 0.f;
    }
    __syncthreads();
    int r = t >> 3, j = t & 7;
    int gn = n0 + r;
    if (gn < M) {
        float a = 0.f;
        #pragma unroll
        for (int k = 0; k < K; k++) a = fmaf(sh[r][k], sf[k * 8 + j], a);
        g_asd[gn * 8 + j] = a;
    }
}

// ---------------- single-pass softmax aggregation ----------------
// exp(a - m)/sum == exp(a)/sum exactly; |alpha| is O(1) here so no overflow.
__global__ __launch_bounds__(256) void agg_kernel(const float* __restrict__ x,
                                                  const float* __restrict__ bias,
                                                  float* __restrict__ hout,
                                                  int nbase, int ncount, int aeoff, int outbase) {
    int lane = threadIdx.x & 31, w = threadIdx.x >> 5;
    int n = nbase + blockIdx.x * 8 + w;
    if (n >= nbase + ncount) return;
    int off = g_rowptr[n];
    int deg = g_rowptr[n + 1] - off;
    int hl = lane >> 3;                         // head for this lane
    float adh = g_asd[n * 8 + 4 + hl];          // dst attention term

    float4 acc = make_float4(0.f, 0.f, 0.f, 0.f);
    float den = 0.f;
    #pragma unroll 4
    for (int i = 0; i < deg; i++) {
        int s = g_csr_src[off + i];
        float aeh = g_csr_ae[(size_t)(off + i) * 8 + aeoff + hl];
        float ash = g_asd[s * 8 + hl];
        float ex = __expf(lrelu(ash + adh + aeh));
        den += ex;
        const float4 xv = *(const float4*)&x[(size_t)s * HC + lane * 4];
        acc.x = fmaf(ex, xv.x, acc.x);
        acc.y = fmaf(ex, xv.y, acc.y);
        acc.z = fmaf(ex, xv.z, acc.z);
        acc.w = fmaf(ex, xv.w, acc.w);
    }
    float inv = 1.f / (den + 1e-16f);
    float4 b4 = *(const float4*)&bias[lane * 4];
    float4 r;
    r.x = fmaf(acc.x, inv, b4.x);
    r.y = fmaf(acc.y, inv, b4.y);
    r.z = fmaf(acc.z, inv, b4.z);
    r.w = fmaf(acc.w, inv, b4.w);
    r.x = r.x > 0.f ? r.x : expm1f(r.x);
    r.y = r.y > 0.f ? r.y : expm1f(r.y);
    r.z = r.z > 0.f ? r.z : expm1f(r.z);
    r.w = r.w > 0.f ? r.w : expm1f(r.w);
    *(float4*)&hout[(size_t)(n - outbase) * HC + lane * 4] = r;
}

// ---------------- mlp2 ----------------
__global__ void mlp2_kernel(const float* __restrict__ hid, const float* __restrict__ Wm2,
                            const float* __restrict__ bm2, float* __restrict__ out) {
    __shared__ float sW[FFH * ODIM];
    __shared__ float sb[ODIM];
    int t = threadIdx.x;
    if (t < FFH * ODIM) sW[t] = Wm2[t];
    if (t < ODIM) sb[t] = bm2[t];
    __syncthreads();
    int n = blockIdx.x * 256 + t;
    if (n >= NWAT) return;
    float a0 = sb[0], a1 = sb[1];
    #pragma unroll 4
    for (int k = 0; k < FFH; k++) {
        float v = hid[(size_t)n * FFH + k];
        a0 = fmaf(v, sW[2 * k], a0);
        a1 = fmaf(v, sW[2 * k + 1], a1);
    }
    out[n * 2] = a0;
    out[n * 2 + 1] = a1;
}

// ---------------- launch ----------------
extern "C" void kernel_launch(void* const* d_in, const int* in_sizes, int n_in,
                              void* d_out, int out_size) {
    static float *p_x = nullptr, *p_h1 = nullptr, *p_h2 = nullptr;
    if (!p_x) {
        cudaGetSymbolAddress((void**)&p_x,  g_x);
        cudaGetSymbolAddress((void**)&p_h1, g_h1);
        cudaGetSymbolAddress((void**)&p_h2, g_h2);
    }

    const float* ppos  = (const float*)d_in[0];
    const float* wpos  = (const float*)d_in[1];
    const float* pf    = (const float*)d_in[2];
    const int*   ei    = (const int*)d_in[3];
    const float* gamma = (const float*)d_in[4];
    const float* Wf    = (const float*)d_in[5];
    const float* bf    = (const float*)d_in[6];
    const float* We    = (const float*)d_in[7];
    const float* be    = (const float*)d_in[8];
    const float* W1    = (const float*)d_in[9];
    const float* atts1 = (const float*)d_in[10];
    const float* attd1 = (const float*)d_in[11];
    const float* Wedge1= (const float*)d_in[12];
    const float* atte1 = (const float*)d_in[13];
    const float* b1    = (const float*)d_in[14];
    const float* W2    = (const float*)d_in[15];
    const float* atts2 = (const float*)d_in[16];
    const float* attd2 = (const float*)d_in[17];
    const float* Wedge2= (const float*)d_in[18];
    const float* atte2 = (const float*)d_in[19];
    const float* b2    = (const float*)d_in[20];
    const float* Wm1   = (const float*)d_in[21];
    const float* bm1   = (const float*)d_in[22];
    const float* Wm2   = (const float*)d_in[23];
    const float* bm2   = (const float*)d_in[24];
    float* out = (float*)d_out;

    const int EB = (EE + 255) / 256;
    const int NB = (NN + 255) / 256;
    const int SB = (NN + 1023) / 1024;

    fold_kernel<<<1, 256>>>(We, be, Wedge1, atte1, Wedge2, atte2,
                            W1, atts1, attd1, W2, atts2, attd2, Wf, bf);
    zero_kernel<<<NB, 256>>>();
    count_kernel<<<EB, 256>>>(ei);
    scan1_kernel<<<SB, 1024>>>();
    scan2_kernel<<<1, 1>>>(SB);
    scan3_kernel<<<NB, 256>>>();
    edge_scatter<<<EB, 256>>>(ei, ppos, wpos, gamma);

    // layer 1: fused h0+gemm1+asd1
    node1_kernel<<<NB, 256>>>(pf);
    agg_kernel<<<(NN + 7) / 8, 256>>>(p_x, b1, p_h1, 0, NN, 0, 0);

    // layer 2 (tensor-core GEMM; aggregate only water dst nodes)
    gemm_tc128<false, false><<<(NN + 127) / 128, 256>>>(p_h1, W2, nullptr, p_x, NN);
    asd_kernel<128><<<(NN + 31) / 32, 256>>>(p_h1, FOLD_ASD2, NN);
    agg_kernel<<<(NWAT + 7) / 8, 256>>>(p_x, b2, p_h2, NPRO, NWAT, 4, NPRO);

    // MLP on water nodes only (tensor-core)
    gemm_tc128<true, true><<<(NWAT + 127) / 128, 256>>>(p_h2, Wm1, bm1, p_x, NWAT);
    mlp2_kernel<<<(NWAT + 255) / 256, 256>>>(p_x, Wm2, bm2, out);
}